// round 6
// baseline (speedup 1.0000x reference)
#include <cuda_runtime.h>
#include <math.h>

// Problem constants
#define BATCH 65536
#define HID   256
#define MID   300
#define MIDP  320      // MID padded to a multiple of 64 for clean GEMM tiles
#define THRS  0.6f

// ---------------------------------------------------------------------------
// Scratch (device globals: allocation-free workaround per harness rules)
// ---------------------------------------------------------------------------
__device__ float g_W1p[3 * HID * MIDP];               // padded W1 (256x320) x3
__device__ float g_b1p[3 * MIDP];                     // padded b1 x3
__device__ float g_W2p[3 * MIDP * HID];               // padded W2 (320x256) x3
__device__ float g_H  [(size_t)BATCH * MIDP];         // encoder hidden (reused x3)
__device__ float g_E  [3 * (size_t)BATCH * HID];      // eb, ef, ep
__device__ float g_C  [(size_t)BATCH * HID];          // common_features
__device__ float g_Z  [(size_t)BATCH * 2 * HID];      // concat(weighted, common*enh)

// ---------------------------------------------------------------------------
// Weight padding: W1 (256x300 -> 256x320 cols zero), b1 (300->320),
// W2 (300x256 -> 320x256 rows zero).
// ---------------------------------------------------------------------------
__global__ void prep_kernel(const float* __restrict__ W1b, const float* __restrict__ W1f,
                            const float* __restrict__ W1p, const float* __restrict__ b1b,
                            const float* __restrict__ b1f, const float* __restrict__ b1p,
                            const float* __restrict__ W2b, const float* __restrict__ W2f,
                            const float* __restrict__ W2p)
{
    const float* W1s[3] = {W1b, W1f, W1p};
    const float* b1s[3] = {b1b, b1f, b1p};
    const float* W2s[3] = {W2b, W2f, W2p};
    const int stride = gridDim.x * blockDim.x;
    const int t0 = blockIdx.x * blockDim.x + threadIdx.x;
    for (int e = 0; e < 3; e++) {
        for (int idx = t0; idx < HID * MIDP; idx += stride) {
            int r = idx / MIDP, c = idx % MIDP;
            g_W1p[e * HID * MIDP + idx] = (c < MID) ? W1s[e][r * MID + c] : 0.f;
        }
        for (int idx = t0; idx < MIDP; idx += stride)
            g_b1p[e * MIDP + idx] = (idx < MID) ? b1s[e][idx] : 0.f;
        for (int idx = t0; idx < MIDP * HID; idx += stride)
            g_W2p[e * MIDP * HID + idx] = (idx < MID * HID) ? W2s[e][idx] : 0.f;
    }
}

// ---------------------------------------------------------------------------
// Tiled fp32 GEMM: C[M,N] = epilogue(A[M,K] @ B[K,N] + bias[N])
// BM=128, BN=64, BK=16, 256 threads, 8x4 per-thread microtile.
// EPI: 0 = none, 1 = relu, 2 = mulsrc[m,n] * sigmoid(.)
// Requires: M%128==0, N%64==0, K%16==0 (guaranteed by construction).
// ---------------------------------------------------------------------------
template <int EPI>
__global__ __launch_bounds__(256) void sgemm_kernel(
    const float* __restrict__ A, const float* __restrict__ Bw,
    const float* __restrict__ bias, float* __restrict__ C,
    int M, int N, int K, int ldc, const float* __restrict__ mulsrc)
{
    __shared__ float As[16][132];   // [k][m], padded vs bank conflicts
    __shared__ float Bs[16][64];    // [k][n]

    const int tid = threadIdx.x;
    const int tm = tid >> 4;        // 0..15 (row group of 8)
    const int tn = tid & 15;        // 0..15 (col group of 4)
    const int m0 = blockIdx.y * 128;
    const int n0 = blockIdx.x * 64;

    float acc[8][4];
#pragma unroll
    for (int i = 0; i < 8; i++)
#pragma unroll
        for (int j = 0; j < 4; j++) acc[i][j] = 0.f;

    for (int k0 = 0; k0 < K; k0 += 16) {
        // load A tile (128x16) transposed into As
#pragma unroll
        for (int i = 0; i < 2; i++) {
            int lin = tid * 2 + i;          // 0..511
            int ar  = lin >> 2;             // 0..127
            int ac  = (lin & 3) << 2;       // 0,4,8,12
            float4 v = *(const float4*)(A + (size_t)(m0 + ar) * K + k0 + ac);
            As[ac + 0][ar] = v.x;
            As[ac + 1][ar] = v.y;
            As[ac + 2][ar] = v.z;
            As[ac + 3][ar] = v.w;
        }
        // load B tile (16x64)
        {
            int br = tid >> 4;
            int bc = (tid & 15) << 2;
            *(float4*)&Bs[br][bc] =
                *(const float4*)(Bw + (size_t)(k0 + br) * N + n0 + bc);
        }
        __syncthreads();

#pragma unroll
        for (int k = 0; k < 16; k++) {
            float a[8], b[4];
#pragma unroll
            for (int i = 0; i < 8; i++) a[i] = As[k][tm * 8 + i];
#pragma unroll
            for (int j = 0; j < 4; j++) b[j] = Bs[k][tn * 4 + j];
#pragma unroll
            for (int i = 0; i < 8; i++)
#pragma unroll
                for (int j = 0; j < 4; j++) acc[i][j] = fmaf(a[i], b[j], acc[i][j]);
        }
        __syncthreads();
    }

    const int col0 = n0 + tn * 4;
    float bv[4];
#pragma unroll
    for (int j = 0; j < 4; j++) bv[j] = bias[col0 + j];

#pragma unroll
    for (int i = 0; i < 8; i++) {
        int row = m0 + tm * 8 + i;
        float4 o;
        float* po = (float*)&o;
#pragma unroll
        for (int j = 0; j < 4; j++) {
            float v = acc[i][j] + bv[j];
            if (EPI == 1) v = fmaxf(v, 0.f);
            if (EPI == 2) {
                float s = 1.f / (1.f + expf(-v));
                v = mulsrc[(size_t)row * N + col0 + j] * s;
            }
            po[j] = v;
        }
        *(float4*)(C + (size_t)row * ldc + col0) = o;
    }
}

// ---------------------------------------------------------------------------
// Fusion kernel: one warp per batch row.
// Reads eb/ef/ep rows; computes cosine sims, masked pair softmax, per-element
// common features (with mean fallback), Wg gating softmax, weighted sum.
// Writes: g_C[row] = common_features, g_Z[row][0:256] = weighted.
// ---------------------------------------------------------------------------
__global__ __launch_bounds__(256) void fuse_kernel(const float* __restrict__ Wg,
                                                   const float* __restrict__ bg)
{
    __shared__ float sWg[768 * 3];
    __shared__ float sbg[3];
    const int tid = threadIdx.x;
    for (int i = tid; i < 768 * 3; i += 256) sWg[i] = Wg[i];
    if (tid < 3) sbg[tid] = bg[tid];
    __syncthreads();

    const int warp = tid >> 5;
    const int lane = tid & 31;
    const size_t row = (size_t)blockIdx.x * 8 + warp;

    const float* eb = g_E + row * HID;
    const float* ef = g_E + (size_t)BATCH * HID + row * HID;
    const float* ep = g_E + 2 * (size_t)BATCH * HID + row * HID;

    float4 vb[2], vf[2], vp[2];
#pragma unroll
    for (int i = 0; i < 2; i++) {
        int c4 = (lane + 32 * i) * 4;
        vb[i] = *(const float4*)(eb + c4);
        vf[i] = *(const float4*)(ef + c4);
        vp[i] = *(const float4*)(ep + c4);
    }

    float nb = 0.f, nf = 0.f, npq = 0.f;
    float d01 = 0.f, d02 = 0.f, d12 = 0.f;
    float g0 = 0.f, g1 = 0.f, g2 = 0.f;
#pragma unroll
    for (int i = 0; i < 2; i++) {
        const float* xb = (const float*)&vb[i];
        const float* xf = (const float*)&vf[i];
        const float* xp = (const float*)&vp[i];
#pragma unroll
        for (int j = 0; j < 4; j++) {
            int col = (lane + 32 * i) * 4 + j;
            float b = xb[j], f = xf[j], p = xp[j];
            nb  += b * b;  nf  += f * f;  npq += p * p;
            d01 += b * f;  d02 += b * p;  d12 += f * p;
            const float* wb = sWg + col * 3;
            const float* wf = sWg + (col + 256) * 3;
            const float* wp = sWg + (col + 512) * 3;
            g0 += b * wb[0] + f * wf[0] + p * wp[0];
            g1 += b * wb[1] + f * wf[1] + p * wp[1];
            g2 += b * wb[2] + f * wf[2] + p * wp[2];
        }
    }
#pragma unroll
    for (int o = 16; o > 0; o >>= 1) {
        nb  += __shfl_xor_sync(0xffffffffu, nb,  o);
        nf  += __shfl_xor_sync(0xffffffffu, nf,  o);
        npq += __shfl_xor_sync(0xffffffffu, npq, o);
        d01 += __shfl_xor_sync(0xffffffffu, d01, o);
        d02 += __shfl_xor_sync(0xffffffffu, d02, o);
        d12 += __shfl_xor_sync(0xffffffffu, d12, o);
        g0  += __shfl_xor_sync(0xffffffffu, g0,  o);
        g1  += __shfl_xor_sync(0xffffffffu, g1,  o);
        g2  += __shfl_xor_sync(0xffffffffu, g2,  o);
    }

    float Nb = fmaxf(sqrtf(nb),  1e-12f);
    float Nf = fmaxf(sqrtf(nf),  1e-12f);
    float Np = fmaxf(sqrtf(npq), 1e-12f);
    float s01 = d01 / (Nb * Nf);
    float s02 = d02 / (Nb * Np);
    float s12 = d12 / (Nf * Np);
    bool p0 = s01 > THRS, p1 = s02 > THRS, p2 = s12 > THRS;
    bool has = p0 || p1 || p2;

    float m = -3.4e38f;
    if (p0) m = fmaxf(m, s01);
    if (p1) m = fmaxf(m, s02);
    if (p2) m = fmaxf(m, s12);
    if (!has) m = 0.f;
    float e0 = p0 ? expf(s01 - m) : 0.f;
    float e1 = p1 ? expf(s02 - m) : 0.f;
    float e2 = p2 ? expf(s12 - m) : 0.f;
    float inv = 1.f / fmaxf(e0 + e1 + e2, 1e-12f);
    float w0 = e0 * inv, w1 = e1 * inv, w2 = e2 * inv;

    g0 += sbg[0]; g1 += sbg[1]; g2 += sbg[2];
    float gm = fmaxf(g0, fmaxf(g1, g2));
    float x0 = expf(g0 - gm), x1 = expf(g1 - gm), x2 = expf(g2 - gm);
    float xinv = 1.f / (x0 + x1 + x2);
    float fw0 = x0 * xinv, fw1 = x1 * xinv, fw2 = x2 * xinv;

    float rNb = 1.f / Nb, rNf = 1.f / Nf, rNp = 1.f / Np;
    float* Crow = g_C + row * HID;
    float* Zrow = g_Z + row * (2 * HID);
#pragma unroll
    for (int i = 0; i < 2; i++) {
        const float* xb = (const float*)&vb[i];
        const float* xf = (const float*)&vf[i];
        const float* xp = (const float*)&vp[i];
        float4 oc, ow;
        float* poc = (float*)&oc;
        float* pow_ = (float*)&ow;
#pragma unroll
        for (int j = 0; j < 4; j++) {
            float b = xb[j], f = xf[j], p = xp[j];
            float bn = b * rNb, fn = f * rNf, pn = p * rNp;
            float c0 = (bn * fn > THRS) ? 0.5f * (b + f) : 0.f;
            float c1 = (bn * pn > THRS) ? 0.5f * (b + p) : 0.f;
            float c2 = (fn * pn > THRS) ? 0.5f * (f + p) : 0.f;
            float sc = c0 * w0 + c1 * w1 + c2 * w2;
            poc[j]  = has ? sc : (b + f + p) * (1.f / 3.f);
            pow_[j] = b * fw0 + f * fw1 + p * fw2;
        }
        int c4 = (lane + 32 * i) * 4;
        *(float4*)(Crow + c4) = oc;
        *(float4*)(Zrow + c4) = ow;
    }
}

// ---------------------------------------------------------------------------
// kernel_launch: 10 graph nodes, default stream, no sync, no allocation.
// ---------------------------------------------------------------------------
extern "C" void kernel_launch(void* const* d_in, const int* in_sizes, int n_in,
                              void* d_out, int out_size)
{
    (void)in_sizes; (void)n_in; (void)out_size;

    const float* X[3]  = {(const float*)d_in[0], (const float*)d_in[1], (const float*)d_in[2]};
    const float* W1[3] = {(const float*)d_in[3], (const float*)d_in[7], (const float*)d_in[11]};
    const float* b1[3] = {(const float*)d_in[4], (const float*)d_in[8], (const float*)d_in[12]};
    const float* W2[3] = {(const float*)d_in[5], (const float*)d_in[9], (const float*)d_in[13]};
    const float* b2[3] = {(const float*)d_in[6], (const float*)d_in[10], (const float*)d_in[14]};
    const float* Wg = (const float*)d_in[15];
    const float* bg = (const float*)d_in[16];
    const float* We = (const float*)d_in[17];
    const float* be = (const float*)d_in[18];
    const float* Wf = (const float*)d_in[19];
    const float* bf = (const float*)d_in[20];

    void* p;
    float *W1p, *b1p, *W2p, *Hs, *Es, *Cs, *Zs;
    cudaGetSymbolAddress(&p, g_W1p); W1p = (float*)p;
    cudaGetSymbolAddress(&p, g_b1p); b1p = (float*)p;
    cudaGetSymbolAddress(&p, g_W2p); W2p = (float*)p;
    cudaGetSymbolAddress(&p, g_H);   Hs  = (float*)p;
    cudaGetSymbolAddress(&p, g_E);   Es  = (float*)p;
    cudaGetSymbolAddress(&p, g_C);   Cs  = (float*)p;
    cudaGetSymbolAddress(&p, g_Z);   Zs  = (float*)p;

    // 1) pad weights
    prep_kernel<<<256, 256>>>(W1[0], W1[1], W1[2], b1[0], b1[1], b1[2],
                              W2[0], W2[1], W2[2]);

    const dim3 blk(256);
    // 2) encoders: h = relu(x @ W1p + b1p); e = h @ W2p + b2
    for (int e = 0; e < 3; e++) {
        dim3 g1(MIDP / 64, BATCH / 128);     // (5, 512)
        sgemm_kernel<1><<<g1, blk>>>(X[e], W1p + e * HID * MIDP, b1p + e * MIDP,
                                     Hs, BATCH, MIDP, HID, MIDP, nullptr);
        dim3 g2(HID / 64, BATCH / 128);      // (4, 512)
        sgemm_kernel<0><<<g2, blk>>>(Hs, W2p + e * MIDP * HID, b2[e],
                                     Es + (size_t)e * BATCH * HID,
                                     BATCH, HID, MIDP, HID, nullptr);
    }

    // 3) fusion: common_features -> g_C, weighted -> g_Z[:, 0:256]
    fuse_kernel<<<BATCH / 8, 256>>>(Wg, bg);

    // 4) cm = common * sigmoid(common @ We + be) -> g_Z[:, 256:512]
    dim3 ge(HID / 64, BATCH / 128);
    sgemm_kernel<2><<<ge, blk>>>(Cs, We, be, Zs + HID,
                                 BATCH, HID, HID, 2 * HID, Cs);

    // 5) fused = Z @ Wf + bf -> d_out
    sgemm_kernel<0><<<ge, blk>>>(Zs, Wf, bf, (float*)d_out,
                                 BATCH, HID, 2 * HID, HID, nullptr);
}

// round 7
// speedup vs baseline: 2.3882x; 2.3882x over previous
#include <cuda_runtime.h>
#include <math.h>
#include <stdint.h>

// Problem constants
#define BATCH 65536
#define HID   256
#define MID   300
#define MIDP  320      // MID padded to a multiple of 64 for clean GEMM tiles
#define THRS  0.6f

// ---------------------------------------------------------------------------
// Scratch (device globals: allocation-free workaround per harness rules)
// ---------------------------------------------------------------------------
__device__ float g_W1p[3 * HID * MIDP];               // padded W1 (256x320) x3
__device__ float g_b1p[3 * MIDP];                     // padded b1 x3
__device__ float g_W2p[3 * MIDP * HID];               // padded W2 (320x256) x3
__device__ float g_H  [(size_t)BATCH * MIDP];         // encoder hidden (reused x3)
__device__ float g_E  [3 * (size_t)BATCH * HID];      // eb, ef, ep
__device__ float g_C  [(size_t)BATCH * HID];          // common_features
__device__ float g_Z  [(size_t)BATCH * 2 * HID];      // concat(weighted, common*enh)

// ---------------------------------------------------------------------------
// Weight padding
// ---------------------------------------------------------------------------
__global__ void prep_kernel(const float* __restrict__ W1b, const float* __restrict__ W1f,
                            const float* __restrict__ W1p, const float* __restrict__ b1b,
                            const float* __restrict__ b1f, const float* __restrict__ b1p,
                            const float* __restrict__ W2b, const float* __restrict__ W2f,
                            const float* __restrict__ W2p)
{
    const float* W1s[3] = {W1b, W1f, W1p};
    const float* b1s[3] = {b1b, b1f, b1p};
    const float* W2s[3] = {W2b, W2f, W2p};
    const int stride = gridDim.x * blockDim.x;
    const int t0 = blockIdx.x * blockDim.x + threadIdx.x;
    for (int e = 0; e < 3; e++) {
        for (int idx = t0; idx < HID * MIDP; idx += stride) {
            int r = idx / MIDP, c = idx % MIDP;
            g_W1p[e * HID * MIDP + idx] = (c < MID) ? W1s[e][r * MID + c] : 0.f;
        }
        for (int idx = t0; idx < MIDP; idx += stride)
            g_b1p[e * MIDP + idx] = (idx < MID) ? b1s[e][idx] : 0.f;
        for (int idx = t0; idx < MIDP * HID; idx += stride)
            g_W2p[e * MIDP * HID + idx] = (idx < MID * HID) ? W2s[e][idx] : 0.f;
    }
}

// ---------------------------------------------------------------------------
// TF32 tensor-core GEMM: C[M,N] = epi(A[M,K] @ B[K,N] + bias[N])
// Block 128x64, BK=16, 4 warps, warp tile 64x32 via m16n8k8 tf32 mma.sync.
// EPI: 0 = none, 1 = relu, 2 = mulsrc * sigmoid(.)
// Requires M%128==0, N%64==0, K%16==0.
// ---------------------------------------------------------------------------
__device__ __forceinline__ uint32_t f2tf(float f) {
    uint32_t u;
    asm("cvt.rna.tf32.f32 %0, %1;" : "=r"(u) : "f"(f));
    return u;
}

template <int EPI>
__global__ __launch_bounds__(128) void mma_gemm(
    const float* __restrict__ A, const float* __restrict__ Bw,
    const float* __restrict__ bias, float* __restrict__ C,
    int M, int N, int K, int ldc, const float* __restrict__ mulsrc)
{
    constexpr int AP = 20;   // As pitch (words): conflict-free fragment LDS
    constexpr int BP = 72;   // Bs pitch (words)
    __shared__ uint32_t As[2][128 * AP];
    __shared__ uint32_t Bs[2][16 * BP];

    const int tid  = threadIdx.x;
    const int lane = tid & 31;
    const int warp = tid >> 5;
    const int g    = lane >> 2;          // groupID 0..7
    const int tq   = lane & 3;           // thread-in-group 0..3
    const int wm0  = (warp >> 1) * 64;   // warp m offset in block
    const int wn0  = (warp & 1) * 32;    // warp n offset in block
    const int m0   = blockIdx.y * 128;
    const int n0   = blockIdx.x * 64;

    // global-load mapping
    const int aRow = tid >> 2;           // 0..31 (+32*i)
    const int aCol = (tid & 3) << 2;     // 0,4,8,12
    const int bKr  = tid >> 4;           // 0..7 (+8*i)
    const int bNc  = (tid & 15) << 2;    // 0..60

    float acc[4][4][4];
#pragma unroll
    for (int im = 0; im < 4; im++)
#pragma unroll
        for (int in = 0; in < 4; in++)
#pragma unroll
            for (int r = 0; r < 4; r++) acc[im][in][r] = 0.f;

    float4 aR[4];
    float4 bR[2];

    auto ldg = [&](int k0) {
#pragma unroll
        for (int i = 0; i < 4; i++)
            aR[i] = *(const float4*)(A + (size_t)(m0 + aRow + 32 * i) * K + k0 + aCol);
#pragma unroll
        for (int i = 0; i < 2; i++)
            bR[i] = *(const float4*)(Bw + (size_t)(k0 + bKr + 8 * i) * N + n0 + bNc);
    };

    auto sts = [&](int buf) {
#pragma unroll
        for (int i = 0; i < 4; i++) {
            uint4 v = make_uint4(f2tf(aR[i].x), f2tf(aR[i].y), f2tf(aR[i].z), f2tf(aR[i].w));
            *(uint4*)&As[buf][(aRow + 32 * i) * AP + aCol] = v;
        }
#pragma unroll
        for (int i = 0; i < 2; i++) {
            uint4 v = make_uint4(f2tf(bR[i].x), f2tf(bR[i].y), f2tf(bR[i].z), f2tf(bR[i].w));
            *(uint4*)&Bs[buf][(bKr + 8 * i) * BP + bNc] = v;
        }
    };

    auto comp = [&](int buf) {
#pragma unroll
        for (int ks = 0; ks < 16; ks += 8) {
            uint32_t af[4][4], bf[4][2];
#pragma unroll
            for (int im = 0; im < 4; im++) {
                int mb = wm0 + im * 16 + g;
                af[im][0] = As[buf][mb * AP + ks + tq];
                af[im][1] = As[buf][(mb + 8) * AP + ks + tq];
                af[im][2] = As[buf][mb * AP + ks + tq + 4];
                af[im][3] = As[buf][(mb + 8) * AP + ks + tq + 4];
            }
#pragma unroll
            for (int in = 0; in < 4; in++) {
                int nn = wn0 + in * 8 + g;
                bf[in][0] = Bs[buf][(ks + tq) * BP + nn];
                bf[in][1] = Bs[buf][(ks + tq + 4) * BP + nn];
            }
#pragma unroll
            for (int im = 0; im < 4; im++)
#pragma unroll
                for (int in = 0; in < 4; in++) {
                    float* c = acc[im][in];
                    asm volatile(
                        "mma.sync.aligned.m16n8k8.row.col.f32.tf32.tf32.f32 "
                        "{%0,%1,%2,%3}, {%4,%5,%6,%7}, {%8,%9}, {%0,%1,%2,%3};"
                        : "+f"(c[0]), "+f"(c[1]), "+f"(c[2]), "+f"(c[3])
                        : "r"(af[im][0]), "r"(af[im][1]), "r"(af[im][2]), "r"(af[im][3]),
                          "r"(bf[in][0]), "r"(bf[in][1]));
                }
        }
    };

    const int nt = K >> 4;
    ldg(0);
    sts(0);
    __syncthreads();
    for (int t = 0; t < nt; t++) {
        if (t + 1 < nt) ldg((t + 1) << 4);
        comp(t & 1);
        if (t + 1 < nt) sts((t + 1) & 1);
        __syncthreads();
    }

    // epilogue
#pragma unroll
    for (int im = 0; im < 4; im++) {
        int r0 = m0 + wm0 + im * 16 + g;
#pragma unroll
        for (int in = 0; in < 4; in++) {
            int col = n0 + wn0 + in * 8 + tq * 2;
            float bv0 = bias[col], bv1 = bias[col + 1];
            float v0 = acc[im][in][0] + bv0;
            float v1 = acc[im][in][1] + bv1;
            float v2 = acc[im][in][2] + bv0;
            float v3 = acc[im][in][3] + bv1;
            if (EPI == 1) {
                v0 = fmaxf(v0, 0.f); v1 = fmaxf(v1, 0.f);
                v2 = fmaxf(v2, 0.f); v3 = fmaxf(v3, 0.f);
            }
            if (EPI == 2) {
                float2 m0v = *(const float2*)(mulsrc + (size_t)r0 * N + col);
                float2 m1v = *(const float2*)(mulsrc + (size_t)(r0 + 8) * N + col);
                v0 = m0v.x / (1.f + expf(-v0));
                v1 = m0v.y / (1.f + expf(-v1));
                v2 = m1v.x / (1.f + expf(-v2));
                v3 = m1v.y / (1.f + expf(-v3));
            }
            *(float2*)(C + (size_t)r0 * ldc + col)       = make_float2(v0, v1);
            *(float2*)(C + (size_t)(r0 + 8) * ldc + col) = make_float2(v2, v3);
        }
    }
}

// ---------------------------------------------------------------------------
// Fusion kernel: one warp per batch row (unchanged from fp32 version).
// ---------------------------------------------------------------------------
__global__ __launch_bounds__(256) void fuse_kernel(const float* __restrict__ Wg,
                                                   const float* __restrict__ bg)
{
    __shared__ float sWg[768 * 3];
    __shared__ float sbg[3];
    const int tid = threadIdx.x;
    for (int i = tid; i < 768 * 3; i += 256) sWg[i] = Wg[i];
    if (tid < 3) sbg[tid] = bg[tid];
    __syncthreads();

    const int warp = tid >> 5;
    const int lane = tid & 31;
    const size_t row = (size_t)blockIdx.x * 8 + warp;

    const float* eb = g_E + row * HID;
    const float* ef = g_E + (size_t)BATCH * HID + row * HID;
    const float* ep = g_E + 2 * (size_t)BATCH * HID + row * HID;

    float4 vb[2], vf[2], vp[2];
#pragma unroll
    for (int i = 0; i < 2; i++) {
        int c4 = (lane + 32 * i) * 4;
        vb[i] = *(const float4*)(eb + c4);
        vf[i] = *(const float4*)(ef + c4);
        vp[i] = *(const float4*)(ep + c4);
    }

    float nb = 0.f, nf = 0.f, npq = 0.f;
    float d01 = 0.f, d02 = 0.f, d12 = 0.f;
    float g0 = 0.f, g1 = 0.f, g2 = 0.f;
#pragma unroll
    for (int i = 0; i < 2; i++) {
        const float* xb = (const float*)&vb[i];
        const float* xf = (const float*)&vf[i];
        const float* xp = (const float*)&vp[i];
#pragma unroll
        for (int j = 0; j < 4; j++) {
            int col = (lane + 32 * i) * 4 + j;
            float b = xb[j], f = xf[j], p = xp[j];
            nb  += b * b;  nf  += f * f;  npq += p * p;
            d01 += b * f;  d02 += b * p;  d12 += f * p;
            const float* wb = sWg + col * 3;
            const float* wf = sWg + (col + 256) * 3;
            const float* wp = sWg + (col + 512) * 3;
            g0 += b * wb[0] + f * wf[0] + p * wp[0];
            g1 += b * wb[1] + f * wf[1] + p * wp[1];
            g2 += b * wb[2] + f * wf[2] + p * wp[2];
        }
    }
#pragma unroll
    for (int o = 16; o > 0; o >>= 1) {
        nb  += __shfl_xor_sync(0xffffffffu, nb,  o);
        nf  += __shfl_xor_sync(0xffffffffu, nf,  o);
        npq += __shfl_xor_sync(0xffffffffu, npq, o);
        d01 += __shfl_xor_sync(0xffffffffu, d01, o);
        d02 += __shfl_xor_sync(0xffffffffu, d02, o);
        d12 += __shfl_xor_sync(0xffffffffu, d12, o);
        g0  += __shfl_xor_sync(0xffffffffu, g0,  o);
        g1  += __shfl_xor_sync(0xffffffffu, g1,  o);
        g2  += __shfl_xor_sync(0xffffffffu, g2,  o);
    }

    float Nb = fmaxf(sqrtf(nb),  1e-12f);
    float Nf = fmaxf(sqrtf(nf),  1e-12f);
    float Np = fmaxf(sqrtf(npq), 1e-12f);
    float s01 = d01 / (Nb * Nf);
    float s02 = d02 / (Nb * Np);
    float s12 = d12 / (Nf * Np);
    bool p0 = s01 > THRS, p1 = s02 > THRS, p2 = s12 > THRS;
    bool has = p0 || p1 || p2;

    float m = -3.4e38f;
    if (p0) m = fmaxf(m, s01);
    if (p1) m = fmaxf(m, s02);
    if (p2) m = fmaxf(m, s12);
    if (!has) m = 0.f;
    float e0 = p0 ? expf(s01 - m) : 0.f;
    float e1 = p1 ? expf(s02 - m) : 0.f;
    float e2 = p2 ? expf(s12 - m) : 0.f;
    float inv = 1.f / fmaxf(e0 + e1 + e2, 1e-12f);
    float w0 = e0 * inv, w1 = e1 * inv, w2 = e2 * inv;

    g0 += sbg[0]; g1 += sbg[1]; g2 += sbg[2];
    float gm = fmaxf(g0, fmaxf(g1, g2));
    float x0 = expf(g0 - gm), x1 = expf(g1 - gm), x2 = expf(g2 - gm);
    float xinv = 1.f / (x0 + x1 + x2);
    float fw0 = x0 * xinv, fw1 = x1 * xinv, fw2 = x2 * xinv;

    float rNb = 1.f / Nb, rNf = 1.f / Nf, rNp = 1.f / Np;
    float* Crow = g_C + row * HID;
    float* Zrow = g_Z + row * (2 * HID);
#pragma unroll
    for (int i = 0; i < 2; i++) {
        const float* xb = (const float*)&vb[i];
        const float* xf = (const float*)&vf[i];
        const float* xp = (const float*)&vp[i];
        float4 oc, ow;
        float* poc = (float*)&oc;
        float* pow_ = (float*)&ow;
#pragma unroll
        for (int j = 0; j < 4; j++) {
            float b = xb[j], f = xf[j], p = xp[j];
            float bn = b * rNb, fn = f * rNf, pn = p * rNp;
            float c0 = (bn * fn > THRS) ? 0.5f * (b + f) : 0.f;
            float c1 = (bn * pn > THRS) ? 0.5f * (b + p) : 0.f;
            float c2 = (fn * pn > THRS) ? 0.5f * (f + p) : 0.f;
            float sc = c0 * w0 + c1 * w1 + c2 * w2;
            poc[j]  = has ? sc : (b + f + p) * (1.f / 3.f);
            pow_[j] = b * fw0 + f * fw1 + p * fw2;
        }
        int c4 = (lane + 32 * i) * 4;
        *(float4*)(Crow + c4) = oc;
        *(float4*)(Zrow + c4) = ow;
    }
}

// ---------------------------------------------------------------------------
// kernel_launch
// ---------------------------------------------------------------------------
extern "C" void kernel_launch(void* const* d_in, const int* in_sizes, int n_in,
                              void* d_out, int out_size)
{
    (void)in_sizes; (void)n_in; (void)out_size;

    const float* X[3]  = {(const float*)d_in[0], (const float*)d_in[1], (const float*)d_in[2]};
    const float* W1[3] = {(const float*)d_in[3], (const float*)d_in[7], (const float*)d_in[11]};
    const float* b1[3] = {(const float*)d_in[4], (const float*)d_in[8], (const float*)d_in[12]};
    const float* W2[3] = {(const float*)d_in[5], (const float*)d_in[9], (const float*)d_in[13]};
    const float* b2[3] = {(const float*)d_in[6], (const float*)d_in[10], (const float*)d_in[14]};
    const float* Wg = (const float*)d_in[15];
    const float* bg = (const float*)d_in[16];
    const float* We = (const float*)d_in[17];
    const float* be = (const float*)d_in[18];
    const float* Wf = (const float*)d_in[19];
    const float* bf = (const float*)d_in[20];

    void* p;
    float *W1p, *b1p, *W2p, *Hs, *Es, *Cs, *Zs;
    cudaGetSymbolAddress(&p, g_W1p); W1p = (float*)p;
    cudaGetSymbolAddress(&p, g_b1p); b1p = (float*)p;
    cudaGetSymbolAddress(&p, g_W2p); W2p = (float*)p;
    cudaGetSymbolAddress(&p, g_H);   Hs  = (float*)p;
    cudaGetSymbolAddress(&p, g_E);   Es  = (float*)p;
    cudaGetSymbolAddress(&p, g_C);   Cs  = (float*)p;
    cudaGetSymbolAddress(&p, g_Z);   Zs  = (float*)p;

    // 1) pad weights
    prep_kernel<<<256, 256>>>(W1[0], W1[1], W1[2], b1[0], b1[1], b1[2],
                              W2[0], W2[1], W2[2]);

    const dim3 blk(128);
    // 2) encoders: h = relu(x @ W1p + b1p); e = h @ W2p + b2
    for (int e = 0; e < 3; e++) {
        dim3 g1(MIDP / 64, BATCH / 128);     // (5, 512)
        mma_gemm<1><<<g1, blk>>>(X[e], W1p + e * HID * MIDP, b1p + e * MIDP,
                                 Hs, BATCH, MIDP, HID, MIDP, nullptr);
        dim3 g2(HID / 64, BATCH / 128);      // (4, 512)
        mma_gemm<0><<<g2, blk>>>(Hs, W2p + e * MIDP * HID, b2[e],
                                 Es + (size_t)e * BATCH * HID,
                                 BATCH, HID, MIDP, HID, nullptr);
    }

    // 3) fusion: common_features -> g_C, weighted -> g_Z[:, 0:256]
    fuse_kernel<<<BATCH / 8, 256>>>(Wg, bg);

    // 4) cm = common * sigmoid(common @ We + be) -> g_Z[:, 256:512]
    dim3 ge(HID / 64, BATCH / 128);
    mma_gemm<2><<<ge, blk>>>(Cs, We, be, Zs + HID,
                             BATCH, HID, HID, 2 * HID, Cs);

    // 5) fused = Z @ Wf + bf -> d_out
    mma_gemm<0><<<ge, blk>>>(Zs, Wf, bf, (float*)d_out,
                             BATCH, HID, 2 * HID, HID, nullptr);
}

// round 8
// speedup vs baseline: 2.4952x; 1.0448x over previous
#include <cuda_runtime.h>
#include <math.h>
#include <stdint.h>

// Problem constants
#define BATCH 65536
#define HID   256
#define MID   300
#define MIDP  320      // MID padded to a multiple of 64 for clean GEMM tiles
#define THRS  0.6f

// ---------------------------------------------------------------------------
// Scratch (device globals: allocation-free workaround per harness rules)
// ---------------------------------------------------------------------------
__device__ float g_W1p[3 * HID * MIDP];               // padded W1 (256x320) x3
__device__ float g_b1p[3 * MIDP];                     // padded b1 x3
__device__ float g_W2p[3 * MIDP * HID];               // padded W2 (320x256) x3
__device__ float g_H  [(size_t)BATCH * MIDP];         // encoder hidden (reused x3)
__device__ float g_E  [3 * (size_t)BATCH * HID];      // eb, ef, ep
__device__ float g_C  [(size_t)BATCH * HID];          // common_features
__device__ float g_Z  [(size_t)BATCH * 2 * HID];      // concat(weighted, common*enh)

// ---------------------------------------------------------------------------
// Weight padding
// ---------------------------------------------------------------------------
__global__ void prep_kernel(const float* __restrict__ W1b, const float* __restrict__ W1f,
                            const float* __restrict__ W1p, const float* __restrict__ b1b,
                            const float* __restrict__ b1f, const float* __restrict__ b1p,
                            const float* __restrict__ W2b, const float* __restrict__ W2f,
                            const float* __restrict__ W2p)
{
    const float* W1s[3] = {W1b, W1f, W1p};
    const float* b1s[3] = {b1b, b1f, b1p};
    const float* W2s[3] = {W2b, W2f, W2p};
    const int stride = gridDim.x * blockDim.x;
    const int t0 = blockIdx.x * blockDim.x + threadIdx.x;
    for (int e = 0; e < 3; e++) {
        for (int idx = t0; idx < HID * MIDP; idx += stride) {
            int r = idx / MIDP, c = idx % MIDP;
            g_W1p[e * HID * MIDP + idx] = (c < MID) ? W1s[e][r * MID + c] : 0.f;
        }
        for (int idx = t0; idx < MIDP; idx += stride)
            g_b1p[e * MIDP + idx] = (idx < MID) ? b1s[e][idx] : 0.f;
        for (int idx = t0; idx < MIDP * HID; idx += stride)
            g_W2p[e * MIDP * HID + idx] = (idx < MID * HID) ? W2s[e][idx] : 0.f;
    }
}

// ---------------------------------------------------------------------------
// TF32 tensor-core GEMM: C[M,N] = epi(A[M,K] @ B[K,N] + bias[N])
// Block 256x64, BK=16, 4 warps, warp tile 64x64 via m16n8k8 tf32 mma.sync.
// Single-buffered smem (25KB) -> 2 blocks/SM; gmem prefetch in registers.
// EPI: 0 = none, 1 = relu, 2 = mulsrc * sigmoid(.)
// Requires M%256==0, N%64==0, K%16==0.
// ---------------------------------------------------------------------------
__device__ __forceinline__ uint32_t f2tf(float f) {
    uint32_t u;
    asm("cvt.rna.tf32.f32 %0, %1;" : "=r"(u) : "f"(f));
    return u;
}

template <int EPI>
__global__ __launch_bounds__(128, 2) void mma_gemm(
    const float* __restrict__ A, const float* __restrict__ Bw,
    const float* __restrict__ bias, float* __restrict__ C,
    int M, int N, int K, int ldc, const float* __restrict__ mulsrc)
{
    constexpr int AP = 20;   // As pitch (words): 20g mod 32 hits all 8 quads -> conflict-free
    constexpr int BP = 72;   // Bs pitch (words): 72 mod 32 = 8 -> conflict-free
    __shared__ uint32_t As[256 * AP];
    __shared__ uint32_t Bs[16 * BP];

    const int tid  = threadIdx.x;
    const int lane = tid & 31;
    const int warp = tid >> 5;
    const int g    = lane >> 2;          // groupID 0..7
    const int tq   = lane & 3;           // thread-in-group 0..3
    const int wm0  = warp * 64;          // warp m offset in block
    const int m0   = blockIdx.y * 256;
    const int n0   = blockIdx.x * 64;

    // global-load mapping
    const int aRow = tid >> 2;           // 0..31 (+32*i, i<8)
    const int aCol = (tid & 3) << 2;     // 0,4,8,12
    const int bKr  = tid >> 4;           // 0..7 (+8*i)
    const int bNc  = (tid & 15) << 2;    // 0..60

    float acc[4][8][4];
#pragma unroll
    for (int im = 0; im < 4; im++)
#pragma unroll
        for (int in = 0; in < 8; in++)
#pragma unroll
            for (int r = 0; r < 4; r++) acc[im][in][r] = 0.f;

    float4 aR[8];
    float4 bR[2];

    auto ldg = [&](int k0) {
#pragma unroll
        for (int i = 0; i < 8; i++)
            aR[i] = *(const float4*)(A + (size_t)(m0 + aRow + 32 * i) * K + k0 + aCol);
#pragma unroll
        for (int i = 0; i < 2; i++)
            bR[i] = *(const float4*)(Bw + (size_t)(k0 + bKr + 8 * i) * N + n0 + bNc);
    };

    auto sts = [&]() {
#pragma unroll
        for (int i = 0; i < 8; i++) {
            uint4 v = make_uint4(f2tf(aR[i].x), f2tf(aR[i].y), f2tf(aR[i].z), f2tf(aR[i].w));
            *(uint4*)&As[(aRow + 32 * i) * AP + aCol] = v;
        }
#pragma unroll
        for (int i = 0; i < 2; i++) {
            uint4 v = make_uint4(f2tf(bR[i].x), f2tf(bR[i].y), f2tf(bR[i].z), f2tf(bR[i].w));
            *(uint4*)&Bs[(bKr + 8 * i) * BP + bNc] = v;
        }
    };

    auto comp = [&]() {
#pragma unroll
        for (int ks = 0; ks < 16; ks += 8) {
            uint32_t af[4][4], bf[8][2];
#pragma unroll
            for (int im = 0; im < 4; im++) {
                int mb = wm0 + im * 16 + g;
                af[im][0] = As[mb * AP + ks + tq];
                af[im][1] = As[(mb + 8) * AP + ks + tq];
                af[im][2] = As[mb * AP + ks + tq + 4];
                af[im][3] = As[(mb + 8) * AP + ks + tq + 4];
            }
#pragma unroll
            for (int in = 0; in < 8; in++) {
                int nn = in * 8 + g;
                bf[in][0] = Bs[(ks + tq) * BP + nn];
                bf[in][1] = Bs[(ks + tq + 4) * BP + nn];
            }
#pragma unroll
            for (int im = 0; im < 4; im++)
#pragma unroll
                for (int in = 0; in < 8; in++) {
                    float* c = acc[im][in];
                    asm volatile(
                        "mma.sync.aligned.m16n8k8.row.col.f32.tf32.tf32.f32 "
                        "{%0,%1,%2,%3}, {%4,%5,%6,%7}, {%8,%9}, {%0,%1,%2,%3};"
                        : "+f"(c[0]), "+f"(c[1]), "+f"(c[2]), "+f"(c[3])
                        : "r"(af[im][0]), "r"(af[im][1]), "r"(af[im][2]), "r"(af[im][3]),
                          "r"(bf[in][0]), "r"(bf[in][1]));
                }
        }
    };

    const int nt = K >> 4;
    ldg(0);
    for (int t = 0; t < nt; t++) {
        __syncthreads();                 // previous tile's readers done
        sts();
        __syncthreads();                 // tile visible
        if (t + 1 < nt) ldg((t + 1) << 4);
        comp();
    }

    // epilogue
#pragma unroll
    for (int im = 0; im < 4; im++) {
        int r0 = m0 + wm0 + im * 16 + g;
#pragma unroll
        for (int in = 0; in < 8; in++) {
            int col = n0 + in * 8 + tq * 2;
            float bv0 = bias[col], bv1 = bias[col + 1];
            float v0 = acc[im][in][0] + bv0;
            float v1 = acc[im][in][1] + bv1;
            float v2 = acc[im][in][2] + bv0;
            float v3 = acc[im][in][3] + bv1;
            if (EPI == 1) {
                v0 = fmaxf(v0, 0.f); v1 = fmaxf(v1, 0.f);
                v2 = fmaxf(v2, 0.f); v3 = fmaxf(v3, 0.f);
            }
            if (EPI == 2) {
                float2 m0v = *(const float2*)(mulsrc + (size_t)r0 * N + col);
                float2 m1v = *(const float2*)(mulsrc + (size_t)(r0 + 8) * N + col);
                v0 = m0v.x / (1.f + expf(-v0));
                v1 = m0v.y / (1.f + expf(-v1));
                v2 = m1v.x / (1.f + expf(-v2));
                v3 = m1v.y / (1.f + expf(-v3));
            }
            *(float2*)(C + (size_t)r0 * ldc + col)       = make_float2(v0, v1);
            *(float2*)(C + (size_t)(r0 + 8) * ldc + col) = make_float2(v2, v3);
        }
    }
}

// ---------------------------------------------------------------------------
// Fusion kernel: one warp per batch row.
// ---------------------------------------------------------------------------
__global__ __launch_bounds__(256) void fuse_kernel(const float* __restrict__ Wg,
                                                   const float* __restrict__ bg)
{
    __shared__ float sWg[768 * 3];
    __shared__ float sbg[3];
    const int tid = threadIdx.x;
    for (int i = tid; i < 768 * 3; i += 256) sWg[i] = Wg[i];
    if (tid < 3) sbg[tid] = bg[tid];
    __syncthreads();

    const int warp = tid >> 5;
    const int lane = tid & 31;
    const size_t row = (size_t)blockIdx.x * 8 + warp;

    const float* eb = g_E + row * HID;
    const float* ef = g_E + (size_t)BATCH * HID + row * HID;
    const float* ep = g_E + 2 * (size_t)BATCH * HID + row * HID;

    float4 vb[2], vf[2], vp[2];
#pragma unroll
    for (int i = 0; i < 2; i++) {
        int c4 = (lane + 32 * i) * 4;
        vb[i] = *(const float4*)(eb + c4);
        vf[i] = *(const float4*)(ef + c4);
        vp[i] = *(const float4*)(ep + c4);
    }

    float nb = 0.f, nf = 0.f, npq = 0.f;
    float d01 = 0.f, d02 = 0.f, d12 = 0.f;
    float g0 = 0.f, g1 = 0.f, g2 = 0.f;
#pragma unroll
    for (int i = 0; i < 2; i++) {
        const float* xb = (const float*)&vb[i];
        const float* xf = (const float*)&vf[i];
        const float* xp = (const float*)&vp[i];
#pragma unroll
        for (int j = 0; j < 4; j++) {
            int col = (lane + 32 * i) * 4 + j;
            float b = xb[j], f = xf[j], p = xp[j];
            nb  += b * b;  nf  += f * f;  npq += p * p;
            d01 += b * f;  d02 += b * p;  d12 += f * p;
            const float* wb = sWg + col * 3;
            const float* wf = sWg + (col + 256) * 3;
            const float* wp = sWg + (col + 512) * 3;
            g0 += b * wb[0] + f * wf[0] + p * wp[0];
            g1 += b * wb[1] + f * wf[1] + p * wp[1];
            g2 += b * wb[2] + f * wf[2] + p * wp[2];
        }
    }
#pragma unroll
    for (int o = 16; o > 0; o >>= 1) {
        nb  += __shfl_xor_sync(0xffffffffu, nb,  o);
        nf  += __shfl_xor_sync(0xffffffffu, nf,  o);
        npq += __shfl_xor_sync(0xffffffffu, npq, o);
        d01 += __shfl_xor_sync(0xffffffffu, d01, o);
        d02 += __shfl_xor_sync(0xffffffffu, d02, o);
        d12 += __shfl_xor_sync(0xffffffffu, d12, o);
        g0  += __shfl_xor_sync(0xffffffffu, g0,  o);
        g1  += __shfl_xor_sync(0xffffffffu, g1,  o);
        g2  += __shfl_xor_sync(0xffffffffu, g2,  o);
    }

    float Nb = fmaxf(sqrtf(nb),  1e-12f);
    float Nf = fmaxf(sqrtf(nf),  1e-12f);
    float Np = fmaxf(sqrtf(npq), 1e-12f);
    float s01 = d01 / (Nb * Nf);
    float s02 = d02 / (Nb * Np);
    float s12 = d12 / (Nf * Np);
    bool p0 = s01 > THRS, p1 = s02 > THRS, p2 = s12 > THRS;
    bool has = p0 || p1 || p2;

    float m = -3.4e38f;
    if (p0) m = fmaxf(m, s01);
    if (p1) m = fmaxf(m, s02);
    if (p2) m = fmaxf(m, s12);
    if (!has) m = 0.f;
    float e0 = p0 ? expf(s01 - m) : 0.f;
    float e1 = p1 ? expf(s02 - m) : 0.f;
    float e2 = p2 ? expf(s12 - m) : 0.f;
    float inv = 1.f / fmaxf(e0 + e1 + e2, 1e-12f);
    float w0 = e0 * inv, w1 = e1 * inv, w2 = e2 * inv;

    g0 += sbg[0]; g1 += sbg[1]; g2 += sbg[2];
    float gm = fmaxf(g0, fmaxf(g1, g2));
    float x0 = expf(g0 - gm), x1 = expf(g1 - gm), x2 = expf(g2 - gm);
    float xinv = 1.f / (x0 + x1 + x2);
    float fw0 = x0 * xinv, fw1 = x1 * xinv, fw2 = x2 * xinv;

    float rNb = 1.f / Nb, rNf = 1.f / Nf, rNp = 1.f / Np;
    float* Crow = g_C + row * HID;
    float* Zrow = g_Z + row * (2 * HID);
#pragma unroll
    for (int i = 0; i < 2; i++) {
        const float* xb = (const float*)&vb[i];
        const float* xf = (const float*)&vf[i];
        const float* xp = (const float*)&vp[i];
        float4 oc, ow;
        float* poc = (float*)&oc;
        float* pow_ = (float*)&ow;
#pragma unroll
        for (int j = 0; j < 4; j++) {
            float b = xb[j], f = xf[j], p = xp[j];
            float bn = b * rNb, fn = f * rNf, pn = p * rNp;
            float c0 = (bn * fn > THRS) ? 0.5f * (b + f) : 0.f;
            float c1 = (bn * pn > THRS) ? 0.5f * (b + p) : 0.f;
            float c2 = (fn * pn > THRS) ? 0.5f * (f + p) : 0.f;
            float sc = c0 * w0 + c1 * w1 + c2 * w2;
            poc[j]  = has ? sc : (b + f + p) * (1.f / 3.f);
            pow_[j] = b * fw0 + f * fw1 + p * fw2;
        }
        int c4 = (lane + 32 * i) * 4;
        *(float4*)(Crow + c4) = oc;
        *(float4*)(Zrow + c4) = ow;
    }
}

// ---------------------------------------------------------------------------
// kernel_launch
// ---------------------------------------------------------------------------
extern "C" void kernel_launch(void* const* d_in, const int* in_sizes, int n_in,
                              void* d_out, int out_size)
{
    (void)in_sizes; (void)n_in; (void)out_size;

    const float* X[3]  = {(const float*)d_in[0], (const float*)d_in[1], (const float*)d_in[2]};
    const float* W1[3] = {(const float*)d_in[3], (const float*)d_in[7], (const float*)d_in[11]};
    const float* b1[3] = {(const float*)d_in[4], (const float*)d_in[8], (const float*)d_in[12]};
    const float* W2[3] = {(const float*)d_in[5], (const float*)d_in[9], (const float*)d_in[13]};
    const float* b2[3] = {(const float*)d_in[6], (const float*)d_in[10], (const float*)d_in[14]};
    const float* Wg = (const float*)d_in[15];
    const float* bg = (const float*)d_in[16];
    const float* We = (const float*)d_in[17];
    const float* be = (const float*)d_in[18];
    const float* Wf = (const float*)d_in[19];
    const float* bf = (const float*)d_in[20];

    void* p;
    float *W1p, *b1p, *W2p, *Hs, *Es, *Cs, *Zs;
    cudaGetSymbolAddress(&p, g_W1p); W1p = (float*)p;
    cudaGetSymbolAddress(&p, g_b1p); b1p = (float*)p;
    cudaGetSymbolAddress(&p, g_W2p); W2p = (float*)p;
    cudaGetSymbolAddress(&p, g_H);   Hs  = (float*)p;
    cudaGetSymbolAddress(&p, g_E);   Es  = (float*)p;
    cudaGetSymbolAddress(&p, g_C);   Cs  = (float*)p;
    cudaGetSymbolAddress(&p, g_Z);   Zs  = (float*)p;

    // 1) pad weights
    prep_kernel<<<256, 256>>>(W1[0], W1[1], W1[2], b1[0], b1[1], b1[2],
                              W2[0], W2[1], W2[2]);

    const dim3 blk(128);
    // 2) encoders: h = relu(x @ W1p + b1p); e = h @ W2p + b2
    for (int e = 0; e < 3; e++) {
        dim3 g1(MIDP / 64, BATCH / 256);     // (5, 256)
        mma_gemm<1><<<g1, blk>>>(X[e], W1p + e * HID * MIDP, b1p + e * MIDP,
                                 Hs, BATCH, MIDP, HID, MIDP, nullptr);
        dim3 g2(HID / 64, BATCH / 256);      // (4, 256)
        mma_gemm<0><<<g2, blk>>>(Hs, W2p + e * MIDP * HID, b2[e],
                                 Es + (size_t)e * BATCH * HID,
                                 BATCH, HID, MIDP, HID, nullptr);
    }

    // 3) fusion: common_features -> g_C, weighted -> g_Z[:, 0:256]
    fuse_kernel<<<BATCH / 8, 256>>>(Wg, bg);

    // 4) cm = common * sigmoid(common @ We + be) -> g_Z[:, 256:512]
    dim3 ge(HID / 64, BATCH / 256);
    mma_gemm<2><<<ge, blk>>>(Cs, We, be, Zs + HID,
                             BATCH, HID, HID, 2 * HID, Cs);

    // 5) fused = Z @ Wf + bf -> d_out
    mma_gemm<0><<<ge, blk>>>(Zs, Wf, bf, (float*)d_out,
                             BATCH, HID, 2 * HID, HID, nullptr);
}

// round 9
// speedup vs baseline: 2.6191x; 1.0497x over previous
#include <cuda_runtime.h>
#include <math.h>
#include <stdint.h>

// Problem constants
#define BATCH 65536
#define HID   256
#define MID   300
#define MIDP  320
#define THRS  0.6f

// ---------------------------------------------------------------------------
// Scratch (device globals)
// ---------------------------------------------------------------------------
__device__ float g_W1p[3 * HID * MIDP];               // padded + tf32-rounded W1 x3
__device__ float g_b1p[3 * MIDP];                     // padded b1 x3 (fp32)
__device__ float g_W2p[3 * MIDP * HID];               // padded + tf32-rounded W2 x3
__device__ float g_b2p[3 * HID];                      // b2 x3 contiguous (fp32)
__device__ float g_Wep[HID * HID];                    // tf32-rounded We
__device__ float g_Wfp[2 * HID * HID];                // tf32-rounded Wf
__device__ float g_X  [3 * (size_t)BATCH * HID];      // tf32-rounded inputs x3
__device__ float g_H  [3 * (size_t)BATCH * MIDP];     // encoder hidden x3 (tf32)
__device__ float g_E  [3 * (size_t)BATCH * HID];      // eb, ef, ep (fp32)
__device__ float g_C  [(size_t)BATCH * HID];          // common_features (tf32)
__device__ float g_Z  [(size_t)BATCH * 2 * HID];      // concat (tf32)

__device__ __forceinline__ float tf32r(float f) {
    uint32_t u;
    asm("cvt.rna.tf32.f32 %0, %1;" : "=r"(u) : "f"(f));
    return __uint_as_float(u);
}

// ---------------------------------------------------------------------------
// prep: pad + tf32-round all weights, concat b2
// ---------------------------------------------------------------------------
__global__ void prep_kernel(const float* __restrict__ W1b, const float* __restrict__ W1f,
                            const float* __restrict__ W1p, const float* __restrict__ b1b,
                            const float* __restrict__ b1f, const float* __restrict__ b1p,
                            const float* __restrict__ W2b, const float* __restrict__ W2f,
                            const float* __restrict__ W2p, const float* __restrict__ b2b,
                            const float* __restrict__ b2f, const float* __restrict__ b2p,
                            const float* __restrict__ We, const float* __restrict__ Wf)
{
    const float* W1s[3] = {W1b, W1f, W1p};
    const float* b1s[3] = {b1b, b1f, b1p};
    const float* W2s[3] = {W2b, W2f, W2p};
    const float* b2s[3] = {b2b, b2f, b2p};
    const int stride = gridDim.x * blockDim.x;
    const int t0 = blockIdx.x * blockDim.x + threadIdx.x;
    for (int e = 0; e < 3; e++) {
        for (int idx = t0; idx < HID * MIDP; idx += stride) {
            int r = idx / MIDP, c = idx % MIDP;
            g_W1p[e * HID * MIDP + idx] = (c < MID) ? tf32r(W1s[e][r * MID + c]) : 0.f;
        }
        for (int idx = t0; idx < MIDP; idx += stride)
            g_b1p[e * MIDP + idx] = (idx < MID) ? b1s[e][idx] : 0.f;
        for (int idx = t0; idx < MIDP * HID; idx += stride)
            g_W2p[e * MIDP * HID + idx] = (idx < MID * HID) ? tf32r(W2s[e][idx]) : 0.f;
        for (int idx = t0; idx < HID; idx += stride)
            g_b2p[e * HID + idx] = b2s[e][idx];
    }
    for (int idx = t0; idx < HID * HID; idx += stride)
        g_Wep[idx] = tf32r(We[idx]);
    for (int idx = t0; idx < 2 * HID * HID; idx += stride)
        g_Wfp[idx] = tf32r(Wf[idx]);
}

// ---------------------------------------------------------------------------
// Convert the 3 input matrices to tf32-rounded scratch (float4 streams)
// ---------------------------------------------------------------------------
__global__ void conv_kernel(const float* __restrict__ x0, const float* __restrict__ x1,
                            const float* __restrict__ x2)
{
    const float* xs = (blockIdx.z == 0) ? x0 : (blockIdx.z == 1) ? x1 : x2;
    float* dst = g_X + (size_t)blockIdx.z * BATCH * HID;
    const size_t n4 = (size_t)BATCH * HID / 4;
    const size_t stride = (size_t)gridDim.x * blockDim.x;
    for (size_t i = blockIdx.x * blockDim.x + threadIdx.x; i < n4; i += stride) {
        float4 v = ((const float4*)xs)[i];
        v.x = tf32r(v.x); v.y = tf32r(v.y); v.z = tf32r(v.z); v.w = tf32r(v.w);
        ((float4*)dst)[i] = v;
    }
}

// ---------------------------------------------------------------------------
// TF32 tensor-core GEMM, cp.async 3-stage pipeline.
// Block 256x64, BK=16, 4 warps, warp tile 64x64, m16n8k8 tf32 mma.sync.
// All operands must be pre-rounded to tf32 (loaded raw via cp.async).
// EPI: 0 = plain fp32 out, 1 = relu + tf32 out, 2 = mulsrc*sigmoid + tf32 out
// z-batched via aZ/bZ/biasZ/cZ element strides.
// ---------------------------------------------------------------------------
#define AP 20                     // As pitch (words), conflict-free + 16B aligned
#define BP 72                     // Bs pitch (words)
#define STAGE_WORDS (256 * AP + 16 * BP)   // 6272
#define SMEM_BYTES (3 * STAGE_WORDS * 4)   // 75264

__device__ __forceinline__ void cp16(uint32_t dst, const float* src) {
    asm volatile("cp.async.cg.shared.global [%0], [%1], 16;\n" :: "r"(dst), "l"(src));
}
__device__ __forceinline__ void cp_commit() { asm volatile("cp.async.commit_group;\n"); }
__device__ __forceinline__ void cp_wait1()  { asm volatile("cp.async.wait_group 1;\n"); }

template <int EPI>
__global__ __launch_bounds__(128, 2) void mma_gemm(
    const float* __restrict__ A, const float* __restrict__ Bw,
    const float* __restrict__ bias, float* __restrict__ C,
    int M, int N, int K, int ldc, const float* __restrict__ mulsrc,
    size_t aZ, size_t bZ, size_t biasZ, size_t cZ)
{
    extern __shared__ uint32_t smem[];
    const uint32_t smem_b = (uint32_t)__cvta_generic_to_shared(smem);

    A    += (size_t)blockIdx.z * aZ;
    Bw   += (size_t)blockIdx.z * bZ;
    bias += (size_t)blockIdx.z * biasZ;
    C    += (size_t)blockIdx.z * cZ;

    const int tid  = threadIdx.x;
    const int lane = tid & 31;
    const int warp = tid >> 5;
    const int g    = lane >> 2;
    const int tq   = lane & 3;
    const int wm0  = warp * 64;
    const int m0   = blockIdx.y * 256;
    const int n0   = blockIdx.x * 64;

    const int aRow = tid >> 2;           // 0..31 (+32*i)
    const int aCol = (tid & 3) << 2;     // 0,4,8,12
    const int bKr  = tid >> 4;           // 0..7 (+8*i)
    const int bNc  = (tid & 15) << 2;    // 0..60

    float acc[4][8][4];
#pragma unroll
    for (int im = 0; im < 4; im++)
#pragma unroll
        for (int in = 0; in < 8; in++)
#pragma unroll
            for (int r = 0; r < 4; r++) acc[im][in][r] = 0.f;

    auto copy_tile = [&](int stage, int k0) {
        uint32_t sb = smem_b + stage * (STAGE_WORDS * 4);
#pragma unroll
        for (int i = 0; i < 8; i++)
            cp16(sb + ((aRow + 32 * i) * AP + aCol) * 4,
                 A + (size_t)(m0 + aRow + 32 * i) * K + k0 + aCol);
        uint32_t bb = sb + 256 * AP * 4;
#pragma unroll
        for (int i = 0; i < 2; i++)
            cp16(bb + ((bKr + 8 * i) * BP + bNc) * 4,
                 Bw + (size_t)(k0 + bKr + 8 * i) * N + n0 + bNc);
    };

    auto comp = [&](int stage) {
        const uint32_t* As = smem + stage * STAGE_WORDS;
        const uint32_t* Bs = As + 256 * AP;
#pragma unroll
        for (int ks = 0; ks < 16; ks += 8) {
            uint32_t af[4][4], bf[8][2];
#pragma unroll
            for (int im = 0; im < 4; im++) {
                int mb = wm0 + im * 16 + g;
                af[im][0] = As[mb * AP + ks + tq];
                af[im][1] = As[(mb + 8) * AP + ks + tq];
                af[im][2] = As[mb * AP + ks + tq + 4];
                af[im][3] = As[(mb + 8) * AP + ks + tq + 4];
            }
#pragma unroll
            for (int in = 0; in < 8; in++) {
                int nn = in * 8 + g;
                bf[in][0] = Bs[(ks + tq) * BP + nn];
                bf[in][1] = Bs[(ks + tq + 4) * BP + nn];
            }
#pragma unroll
            for (int im = 0; im < 4; im++)
#pragma unroll
                for (int in = 0; in < 8; in++) {
                    float* c = acc[im][in];
                    asm volatile(
                        "mma.sync.aligned.m16n8k8.row.col.f32.tf32.tf32.f32 "
                        "{%0,%1,%2,%3}, {%4,%5,%6,%7}, {%8,%9}, {%0,%1,%2,%3};"
                        : "+f"(c[0]), "+f"(c[1]), "+f"(c[2]), "+f"(c[3])
                        : "r"(af[im][0]), "r"(af[im][1]), "r"(af[im][2]), "r"(af[im][3]),
                          "r"(bf[in][0]), "r"(bf[in][1]));
                }
        }
    };

    const int nt = K >> 4;
    // prologue: tiles 0,1 into stages 0,1 (nt >= 16 always)
    copy_tile(0, 0);  cp_commit();
    copy_tile(1, 16); cp_commit();

    for (int t = 0; t < nt; t++) {
        cp_wait1();                      // tile t landed
        __syncthreads();                 // visible to all; all done with stage (t+2)%3
        if (t + 2 < nt) copy_tile((t + 2) % 3, (t + 2) << 4);
        cp_commit();
        comp(t % 3);
    }

    // epilogue
#pragma unroll
    for (int im = 0; im < 4; im++) {
        int r0 = m0 + wm0 + im * 16 + g;
#pragma unroll
        for (int in = 0; in < 8; in++) {
            int col = n0 + in * 8 + tq * 2;
            float bv0 = bias[col], bv1 = bias[col + 1];
            float v0 = acc[im][in][0] + bv0;
            float v1 = acc[im][in][1] + bv1;
            float v2 = acc[im][in][2] + bv0;
            float v3 = acc[im][in][3] + bv1;
            if (EPI == 1) {
                v0 = tf32r(fmaxf(v0, 0.f)); v1 = tf32r(fmaxf(v1, 0.f));
                v2 = tf32r(fmaxf(v2, 0.f)); v3 = tf32r(fmaxf(v3, 0.f));
            }
            if (EPI == 2) {
                float2 m0v = *(const float2*)(mulsrc + (size_t)r0 * N + col);
                float2 m1v = *(const float2*)(mulsrc + (size_t)(r0 + 8) * N + col);
                v0 = tf32r(m0v.x / (1.f + expf(-v0)));
                v1 = tf32r(m0v.y / (1.f + expf(-v1)));
                v2 = tf32r(m1v.x / (1.f + expf(-v2)));
                v3 = tf32r(m1v.y / (1.f + expf(-v3)));
            }
            *(float2*)(C + (size_t)r0 * ldc + col)       = make_float2(v0, v1);
            *(float2*)(C + (size_t)(r0 + 8) * ldc + col) = make_float2(v2, v3);
        }
    }
}

// ---------------------------------------------------------------------------
// Fusion kernel: one warp per batch row. Outputs tf32-rounded C and Z[:,0:256].
// ---------------------------------------------------------------------------
__global__ __launch_bounds__(256) void fuse_kernel(const float* __restrict__ Wg,
                                                   const float* __restrict__ bg)
{
    __shared__ float sWg[768 * 3];
    __shared__ float sbg[3];
    const int tid = threadIdx.x;
    for (int i = tid; i < 768 * 3; i += 256) sWg[i] = Wg[i];
    if (tid < 3) sbg[tid] = bg[tid];
    __syncthreads();

    const int warp = tid >> 5;
    const int lane = tid & 31;
    const size_t row = (size_t)blockIdx.x * 8 + warp;

    const float* eb = g_E + row * HID;
    const float* ef = g_E + (size_t)BATCH * HID + row * HID;
    const float* ep = g_E + 2 * (size_t)BATCH * HID + row * HID;

    float4 vb[2], vf[2], vp[2];
#pragma unroll
    for (int i = 0; i < 2; i++) {
        int c4 = (lane + 32 * i) * 4;
        vb[i] = *(const float4*)(eb + c4);
        vf[i] = *(const float4*)(ef + c4);
        vp[i] = *(const float4*)(ep + c4);
    }

    float nb = 0.f, nf = 0.f, npq = 0.f;
    float d01 = 0.f, d02 = 0.f, d12 = 0.f;
    float g0 = 0.f, g1 = 0.f, g2 = 0.f;
#pragma unroll
    for (int i = 0; i < 2; i++) {
        const float* xb = (const float*)&vb[i];
        const float* xf = (const float*)&vf[i];
        const float* xp = (const float*)&vp[i];
#pragma unroll
        for (int j = 0; j < 4; j++) {
            int col = (lane + 32 * i) * 4 + j;
            float b = xb[j], f = xf[j], p = xp[j];
            nb  += b * b;  nf  += f * f;  npq += p * p;
            d01 += b * f;  d02 += b * p;  d12 += f * p;
            const float* wb = sWg + col * 3;
            const float* wf = sWg + (col + 256) * 3;
            const float* wp = sWg + (col + 512) * 3;
            g0 += b * wb[0] + f * wf[0] + p * wp[0];
            g1 += b * wb[1] + f * wf[1] + p * wp[1];
            g2 += b * wb[2] + f * wf[2] + p * wp[2];
        }
    }
#pragma unroll
    for (int o = 16; o > 0; o >>= 1) {
        nb  += __shfl_xor_sync(0xffffffffu, nb,  o);
        nf  += __shfl_xor_sync(0xffffffffu, nf,  o);
        npq += __shfl_xor_sync(0xffffffffu, npq, o);
        d01 += __shfl_xor_sync(0xffffffffu, d01, o);
        d02 += __shfl_xor_sync(0xffffffffu, d02, o);
        d12 += __shfl_xor_sync(0xffffffffu, d12, o);
        g0  += __shfl_xor_sync(0xffffffffu, g0,  o);
        g1  += __shfl_xor_sync(0xffffffffu, g1,  o);
        g2  += __shfl_xor_sync(0xffffffffu, g2,  o);
    }

    float Nb = fmaxf(sqrtf(nb),  1e-12f);
    float Nf = fmaxf(sqrtf(nf),  1e-12f);
    float Np = fmaxf(sqrtf(npq), 1e-12f);
    float s01 = d01 / (Nb * Nf);
    float s02 = d02 / (Nb * Np);
    float s12 = d12 / (Nf * Np);
    bool p0 = s01 > THRS, p1 = s02 > THRS, p2 = s12 > THRS;
    bool has = p0 || p1 || p2;

    float m = -3.4e38f;
    if (p0) m = fmaxf(m, s01);
    if (p1) m = fmaxf(m, s02);
    if (p2) m = fmaxf(m, s12);
    if (!has) m = 0.f;
    float e0 = p0 ? expf(s01 - m) : 0.f;
    float e1 = p1 ? expf(s02 - m) : 0.f;
    float e2 = p2 ? expf(s12 - m) : 0.f;
    float inv = 1.f / fmaxf(e0 + e1 + e2, 1e-12f);
    float w0 = e0 * inv, w1 = e1 * inv, w2 = e2 * inv;

    g0 += sbg[0]; g1 += sbg[1]; g2 += sbg[2];
    float gm = fmaxf(g0, fmaxf(g1, g2));
    float x0 = expf(g0 - gm), x1 = expf(g1 - gm), x2 = expf(g2 - gm);
    float xinv = 1.f / (x0 + x1 + x2);
    float fw0 = x0 * xinv, fw1 = x1 * xinv, fw2 = x2 * xinv;

    float rNb = 1.f / Nb, rNf = 1.f / Nf, rNp = 1.f / Np;
    float* Crow = g_C + row * HID;
    float* Zrow = g_Z + row * (2 * HID);
#pragma unroll
    for (int i = 0; i < 2; i++) {
        const float* xb = (const float*)&vb[i];
        const float* xf = (const float*)&vf[i];
        const float* xp = (const float*)&vp[i];
        float4 oc, ow;
        float* poc = (float*)&oc;
        float* pow_ = (float*)&ow;
#pragma unroll
        for (int j = 0; j < 4; j++) {
            float b = xb[j], f = xf[j], p = xp[j];
            float bn = b * rNb, fn = f * rNf, pn = p * rNp;
            float c0 = (bn * fn > THRS) ? 0.5f * (b + f) : 0.f;
            float c1 = (bn * pn > THRS) ? 0.5f * (b + p) : 0.f;
            float c2 = (fn * pn > THRS) ? 0.5f * (f + p) : 0.f;
            float sc = c0 * w0 + c1 * w1 + c2 * w2;
            poc[j]  = tf32r(has ? sc : (b + f + p) * (1.f / 3.f));
            pow_[j] = tf32r(b * fw0 + f * fw1 + p * fw2);
        }
        int c4 = (lane + 32 * i) * 4;
        *(float4*)(Crow + c4) = oc;
        *(float4*)(Zrow + c4) = ow;
    }
}

// ---------------------------------------------------------------------------
// kernel_launch
// ---------------------------------------------------------------------------
extern "C" void kernel_launch(void* const* d_in, const int* in_sizes, int n_in,
                              void* d_out, int out_size)
{
    (void)in_sizes; (void)n_in; (void)out_size;

    const float* X[3]  = {(const float*)d_in[0], (const float*)d_in[1], (const float*)d_in[2]};
    const float* W1[3] = {(const float*)d_in[3], (const float*)d_in[7], (const float*)d_in[11]};
    const float* b1[3] = {(const float*)d_in[4], (const float*)d_in[8], (const float*)d_in[12]};
    const float* W2[3] = {(const float*)d_in[5], (const float*)d_in[9], (const float*)d_in[13]};
    const float* b2[3] = {(const float*)d_in[6], (const float*)d_in[10], (const float*)d_in[14]};
    const float* Wg = (const float*)d_in[15];
    const float* bg = (const float*)d_in[16];
    const float* be = (const float*)d_in[18];
    const float* bf = (const float*)d_in[20];

    void* p;
    float *W1p, *b1p, *W2p, *b2p, *Wep, *Wfp, *Xs, *Hs, *Es, *Cs, *Zs;
    cudaGetSymbolAddress(&p, g_W1p); W1p = (float*)p;
    cudaGetSymbolAddress(&p, g_b1p); b1p = (float*)p;
    cudaGetSymbolAddress(&p, g_W2p); W2p = (float*)p;
    cudaGetSymbolAddress(&p, g_b2p); b2p = (float*)p;
    cudaGetSymbolAddress(&p, g_Wep); Wep = (float*)p;
    cudaGetSymbolAddress(&p, g_Wfp); Wfp = (float*)p;
    cudaGetSymbolAddress(&p, g_X);   Xs  = (float*)p;
    cudaGetSymbolAddress(&p, g_H);   Hs  = (float*)p;
    cudaGetSymbolAddress(&p, g_E);   Es  = (float*)p;
    cudaGetSymbolAddress(&p, g_C);   Cs  = (float*)p;
    cudaGetSymbolAddress(&p, g_Z);   Zs  = (float*)p;

    cudaFuncSetAttribute(mma_gemm<0>, cudaFuncAttributeMaxDynamicSharedMemorySize, SMEM_BYTES);
    cudaFuncSetAttribute(mma_gemm<1>, cudaFuncAttributeMaxDynamicSharedMemorySize, SMEM_BYTES);
    cudaFuncSetAttribute(mma_gemm<2>, cudaFuncAttributeMaxDynamicSharedMemorySize, SMEM_BYTES);

    // 1) pad + round weights; concat b2
    prep_kernel<<<512, 256>>>(W1[0], W1[1], W1[2], b1[0], b1[1], b1[2],
                              W2[0], W2[1], W2[2], b2[0], b2[1], b2[2],
                              (const float*)d_in[17], (const float*)d_in[19]);

    // 2) round inputs into scratch
    {
        dim3 gc(2048, 1, 3);
        conv_kernel<<<gc, 256>>>(X[0], X[1], X[2]);
    }

    const dim3 blk(128);
    // 3) encoders, z-batched over the 3 fingerprints
    {
        dim3 g1(MIDP / 64, BATCH / 256, 3);
        mma_gemm<1><<<g1, blk, SMEM_BYTES>>>(
            Xs, W1p, b1p, Hs, BATCH, MIDP, HID, MIDP, nullptr,
            (size_t)BATCH * HID, (size_t)HID * MIDP, MIDP, (size_t)BATCH * MIDP);
        dim3 g2(HID / 64, BATCH / 256, 3);
        mma_gemm<0><<<g2, blk, SMEM_BYTES>>>(
            Hs, W2p, b2p, Es, BATCH, HID, MIDP, HID, nullptr,
            (size_t)BATCH * MIDP, (size_t)MIDP * HID, HID, (size_t)BATCH * HID);
    }

    // 4) fusion: common -> g_C (tf32), weighted -> g_Z[:,0:256] (tf32)
    fuse_kernel<<<BATCH / 8, 256>>>(Wg, bg);

    // 5) cm = common * sigmoid(common @ We + be) -> g_Z[:,256:512] (tf32)
    dim3 ge(HID / 64, BATCH / 256, 1);
    mma_gemm<2><<<ge, blk, SMEM_BYTES>>>(Cs, Wep, be, Zs + HID,
                                         BATCH, HID, HID, 2 * HID, Cs, 0, 0, 0, 0);

    // 6) fused = Z @ Wf + bf -> d_out (fp32)
    mma_gemm<0><<<ge, blk, SMEM_BYTES>>>(Zs, Wfp, bf, (float*)d_out,
                                         BATCH, HID, 2 * HID, HID, nullptr, 0, 0, 0, 0);
}

// round 11
// speedup vs baseline: 2.6531x; 1.0130x over previous
#include <cuda_runtime.h>
#include <math.h>
#include <stdint.h>

// Problem constants
#define BATCH 65536
#define HID   256
#define MID   300
#define MIDP  320
#define THRS  0.6f

// ---------------------------------------------------------------------------
// Scratch (device globals)
// ---------------------------------------------------------------------------
__device__ float g_W1p[3 * HID * MIDP];               // padded + tf32-rounded W1 x3
__device__ float g_b1p[3 * MIDP];                     // padded b1 x3 (fp32)
__device__ float g_W2p[3 * MIDP * HID];               // padded + tf32-rounded W2 x3
__device__ float g_b2p[3 * HID];                      // b2 x3 contiguous (fp32)
__device__ float g_Wep[HID * HID];                    // tf32-rounded We
__device__ float g_Wfp[2 * HID * HID];                // tf32-rounded Wf
__device__ float g_X  [3 * (size_t)BATCH * HID];      // tf32-rounded inputs x3
__device__ float g_H  [3 * (size_t)BATCH * MIDP];     // encoder hidden x3 (tf32)
__device__ float g_E  [3 * (size_t)BATCH * HID];      // eb, ef, ep (fp32)
__device__ float g_C  [(size_t)BATCH * HID];          // common_features (tf32)
__device__ float g_Z  [(size_t)BATCH * 2 * HID];      // concat (tf32)

__device__ __forceinline__ float tf32r(float f) {
    uint32_t u;
    asm("cvt.rna.tf32.f32 %0, %1;" : "=r"(u) : "f"(f));
    return __uint_as_float(u);
}

// ---------------------------------------------------------------------------
// prep: pad + tf32-round all weights, concat b2
// ---------------------------------------------------------------------------
__global__ void prep_kernel(const float* __restrict__ W1b, const float* __restrict__ W1f,
                            const float* __restrict__ W1p, const float* __restrict__ b1b,
                            const float* __restrict__ b1f, const float* __restrict__ b1p,
                            const float* __restrict__ W2b, const float* __restrict__ W2f,
                            const float* __restrict__ W2p, const float* __restrict__ b2b,
                            const float* __restrict__ b2f, const float* __restrict__ b2p,
                            const float* __restrict__ We, const float* __restrict__ Wf)
{
    const float* W1s[3] = {W1b, W1f, W1p};
    const float* b1s[3] = {b1b, b1f, b1p};
    const float* W2s[3] = {W2b, W2f, W2p};
    const float* b2s[3] = {b2b, b2f, b2p};
    const int stride = gridDim.x * blockDim.x;
    const int t0 = blockIdx.x * blockDim.x + threadIdx.x;
    for (int e = 0; e < 3; e++) {
        for (int idx = t0; idx < HID * MIDP; idx += stride) {
            int r = idx / MIDP, c = idx % MIDP;
            g_W1p[e * HID * MIDP + idx] = (c < MID) ? tf32r(W1s[e][r * MID + c]) : 0.f;
        }
        for (int idx = t0; idx < MIDP; idx += stride)
            g_b1p[e * MIDP + idx] = (idx < MID) ? b1s[e][idx] : 0.f;
        for (int idx = t0; idx < MIDP * HID; idx += stride)
            g_W2p[e * MIDP * HID + idx] = (idx < MID * HID) ? tf32r(W2s[e][idx]) : 0.f;
        for (int idx = t0; idx < HID; idx += stride)
            g_b2p[e * HID + idx] = b2s[e][idx];
    }
    for (int idx = t0; idx < HID * HID; idx += stride)
        g_Wep[idx] = tf32r(We[idx]);
    for (int idx = t0; idx < 2 * HID * HID; idx += stride)
        g_Wfp[idx] = tf32r(Wf[idx]);
}

// ---------------------------------------------------------------------------
// Convert the 3 input matrices to tf32-rounded scratch
// ---------------------------------------------------------------------------
__global__ void conv_kernel(const float* __restrict__ x0, const float* __restrict__ x1,
                            const float* __restrict__ x2)
{
    const float* xs = (blockIdx.z == 0) ? x0 : (blockIdx.z == 1) ? x1 : x2;
    float* dst = g_X + (size_t)blockIdx.z * BATCH * HID;
    const size_t n4 = (size_t)BATCH * HID / 4;
    const size_t stride = (size_t)gridDim.x * blockDim.x;
    for (size_t i = blockIdx.x * blockDim.x + threadIdx.x; i < n4; i += stride) {
        float4 v = ((const float4*)xs)[i];
        v.x = tf32r(v.x); v.y = tf32r(v.y); v.z = tf32r(v.z); v.w = tf32r(v.w);
        ((float4*)dst)[i] = v;
    }
}

// ---------------------------------------------------------------------------
// TF32 tensor-core GEMM, cp.async 3-stage pipeline.
// Block 256x64, BK=16, 8 warps (256 thr), warp tile 32x64, m16n8k8 mma.sync.
// All operands pre-rounded to tf32 (loaded raw via cp.async).
// EPI: 0 = plain fp32 out, 1 = relu + tf32 out, 2 = mulsrc*sigmoid + tf32 out
// z-batched via aZ/bZ/biasZ/cZ element strides.
// ---------------------------------------------------------------------------
#define AP 20                     // As pitch (words), conflict-free + 16B aligned
#define BP 72                     // Bs pitch (words)
#define STAGE_WORDS (256 * AP + 16 * BP)   // 6272
#define SMEM_BYTES (3 * STAGE_WORDS * 4)   // 75264

__device__ __forceinline__ void cp16(uint32_t dst, const float* src) {
    asm volatile("cp.async.cg.shared.global [%0], [%1], 16;\n" :: "r"(dst), "l"(src));
}
__device__ __forceinline__ void cp_commit() { asm volatile("cp.async.commit_group;\n"); }
__device__ __forceinline__ void cp_wait1()  { asm volatile("cp.async.wait_group 1;\n"); }

template <int EPI>
__global__ __launch_bounds__(256, 2) void mma_gemm(
    const float* __restrict__ A, const float* __restrict__ Bw,
    const float* __restrict__ bias, float* __restrict__ C,
    int M, int N, int K, int ldc, const float* __restrict__ mulsrc,
    size_t aZ, size_t bZ, size_t biasZ, size_t cZ)
{
    extern __shared__ uint32_t smem[];
    const uint32_t smem_b = (uint32_t)__cvta_generic_to_shared(smem);

    A    += (size_t)blockIdx.z * aZ;
    Bw   += (size_t)blockIdx.z * bZ;
    bias += (size_t)blockIdx.z * biasZ;
    C    += (size_t)blockIdx.z * cZ;

    const int tid  = threadIdx.x;
    const int lane = tid & 31;
    const int warp = tid >> 5;
    const int g    = lane >> 2;
    const int tq   = lane & 3;
    const int wm0  = warp * 32;          // warp m offset (8 warps x 32 rows)
    const int m0   = blockIdx.y * 256;
    const int n0   = blockIdx.x * 64;

    const int aRow = tid >> 2;           // 0..63 (+64*i, i<4)
    const int aCol = (tid & 3) << 2;     // 0,4,8,12
    const int bKr  = tid >> 4;           // 0..15
    const int bNc  = (tid & 15) << 2;    // 0..60

    float acc[2][8][4];
#pragma unroll
    for (int im = 0; im < 2; im++)
#pragma unroll
        for (int in = 0; in < 8; in++)
#pragma unroll
            for (int r = 0; r < 4; r++) acc[im][in][r] = 0.f;

    auto copy_tile = [&](int stage, int k0) {
        uint32_t sb = smem_b + stage * (STAGE_WORDS * 4);
#pragma unroll
        for (int i = 0; i < 4; i++)
            cp16(sb + ((aRow + 64 * i) * AP + aCol) * 4,
                 A + (size_t)(m0 + aRow + 64 * i) * K + k0 + aCol);
        uint32_t bb = sb + 256 * AP * 4;
        cp16(bb + (bKr * BP + bNc) * 4,
             Bw + (size_t)(k0 + bKr) * N + n0 + bNc);
    };

    auto comp = [&](int stage) {
        const uint32_t* As = smem + stage * STAGE_WORDS;
        const uint32_t* Bs = As + 256 * AP;
#pragma unroll
        for (int ks = 0; ks < 16; ks += 8) {
            uint32_t af[2][4], bf[8][2];
#pragma unroll
            for (int im = 0; im < 2; im++) {
                int mb = wm0 + im * 16 + g;
                af[im][0] = As[mb * AP + ks + tq];
                af[im][1] = As[(mb + 8) * AP + ks + tq];
                af[im][2] = As[mb * AP + ks + tq + 4];
                af[im][3] = As[(mb + 8) * AP + ks + tq + 4];
            }
#pragma unroll
            for (int in = 0; in < 8; in++) {
                int nn = in * 8 + g;
                bf[in][0] = Bs[(ks + tq) * BP + nn];
                bf[in][1] = Bs[(ks + tq + 4) * BP + nn];
            }
#pragma unroll
            for (int im = 0; im < 2; im++)
#pragma unroll
                for (int in = 0; in < 8; in++) {
                    float* c = acc[im][in];
                    asm volatile(
                        "mma.sync.aligned.m16n8k8.row.col.f32.tf32.tf32.f32 "
                        "{%0,%1,%2,%3}, {%4,%5,%6,%7}, {%8,%9}, {%0,%1,%2,%3};"
                        : "+f"(c[0]), "+f"(c[1]), "+f"(c[2]), "+f"(c[3])
                        : "r"(af[im][0]), "r"(af[im][1]), "r"(af[im][2]), "r"(af[im][3]),
                          "r"(bf[in][0]), "r"(bf[in][1]));
                }
        }
    };

    const int nt = K >> 4;
    copy_tile(0, 0);  cp_commit();
    copy_tile(1, 16); cp_commit();

    for (int t = 0; t < nt; t++) {
        cp_wait1();                      // tile t landed
        __syncthreads();                 // visible; all done with stage (t+2)%3
        if (t + 2 < nt) copy_tile((t + 2) % 3, (t + 2) << 4);
        cp_commit();
        comp(t % 3);
    }

    // epilogue
#pragma unroll
    for (int im = 0; im < 2; im++) {
        int r0 = m0 + wm0 + im * 16 + g;
#pragma unroll
        for (int in = 0; in < 8; in++) {
            int col = n0 + in * 8 + tq * 2;
            float bv0 = bias[col], bv1 = bias[col + 1];
            float v0 = acc[im][in][0] + bv0;
            float v1 = acc[im][in][1] + bv1;
            float v2 = acc[im][in][2] + bv0;
            float v3 = acc[im][in][3] + bv1;
            if (EPI == 1) {
                v0 = tf32r(fmaxf(v0, 0.f)); v1 = tf32r(fmaxf(v1, 0.f));
                v2 = tf32r(fmaxf(v2, 0.f)); v3 = tf32r(fmaxf(v3, 0.f));
            }
            if (EPI == 2) {
                float2 m0v = *(const float2*)(mulsrc + (size_t)r0 * N + col);
                float2 m1v = *(const float2*)(mulsrc + (size_t)(r0 + 8) * N + col);
                v0 = tf32r(m0v.x / (1.f + expf(-v0)));
                v1 = tf32r(m0v.y / (1.f + expf(-v1)));
                v2 = tf32r(m1v.x / (1.f + expf(-v2)));
                v3 = tf32r(m1v.y / (1.f + expf(-v3)));
            }
            *(float2*)(C + (size_t)r0 * ldc + col)       = make_float2(v0, v1);
            *(float2*)(C + (size_t)(r0 + 8) * ldc + col) = make_float2(v2, v3);
        }
    }
}

// ---------------------------------------------------------------------------
// Fusion kernel: one warp per batch row (tf32-rounded outputs)
// ---------------------------------------------------------------------------
__global__ __launch_bounds__(256) void fuse_kernel(const float* __restrict__ Wg,
                                                   const float* __restrict__ bg)
{
    __shared__ float sWg[768 * 3];
    __shared__ float sbg[3];
    const int tid = threadIdx.x;
    for (int i = tid; i < 768 * 3; i += 256) sWg[i] = Wg[i];
    if (tid < 3) sbg[tid] = bg[tid];
    __syncthreads();

    const int warp = tid >> 5;
    const int lane = tid & 31;
    const size_t row = (size_t)blockIdx.x * 8 + warp;

    const float* eb = g_E + row * HID;
    const float* ef = g_E + (size_t)BATCH * HID + row * HID;
    const float* ep = g_E + 2 * (size_t)BATCH * HID + row * HID;

    float4 vb[2], vf[2], vp[2];
#pragma unroll
    for (int i = 0; i < 2; i++) {
        int c4 = (lane + 32 * i) * 4;
        vb[i] = *(const float4*)(eb + c4);
        vf[i] = *(const float4*)(ef + c4);
        vp[i] = *(const float4*)(ep + c4);
    }

    float nb = 0.f, nf = 0.f, npq = 0.f;
    float d01 = 0.f, d02 = 0.f, d12 = 0.f;
    float g0 = 0.f, g1 = 0.f, g2 = 0.f;
#pragma unroll
    for (int i = 0; i < 2; i++) {
        const float* xb = (const float*)&vb[i];
        const float* xf = (const float*)&vf[i];
        const float* xp = (const float*)&vp[i];
#pragma unroll
        for (int j = 0; j < 4; j++) {
            int col = (lane + 32 * i) * 4 + j;
            float b = xb[j], f = xf[j], p = xp[j];
            nb  += b * b;  nf  += f * f;  npq += p * p;
            d01 += b * f;  d02 += b * p;  d12 += f * p;
            const float* wb = sWg + col * 3;
            const float* wf = sWg + (col + 256) * 3;
            const float* wp = sWg + (col + 512) * 3;
            g0 += b * wb[0] + f * wf[0] + p * wp[0];
            g1 += b * wb[1] + f * wf[1] + p * wp[1];
            g2 += b * wb[2] + f * wf[2] + p * wp[2];
        }
    }
#pragma unroll
    for (int o = 16; o > 0; o >>= 1) {
        nb  += __shfl_xor_sync(0xffffffffu, nb,  o);
        nf  += __shfl_xor_sync(0xffffffffu, nf,  o);
        npq += __shfl_xor_sync(0xffffffffu, npq, o);
        d01 += __shfl_xor_sync(0xffffffffu, d01, o);
        d02 += __shfl_xor_sync(0xffffffffu, d02, o);
        d12 += __shfl_xor_sync(0xffffffffu, d12, o);
        g0  += __shfl_xor_sync(0xffffffffu, g0,  o);
        g1  += __shfl_xor_sync(0xffffffffu, g1,  o);
        g2  += __shfl_xor_sync(0xffffffffu, g2,  o);
    }

    float Nb = fmaxf(sqrtf(nb),  1e-12f);
    float Nf = fmaxf(sqrtf(nf),  1e-12f);
    float Np = fmaxf(sqrtf(npq), 1e-12f);
    float s01 = d01 / (Nb * Nf);
    float s02 = d02 / (Nb * Np);
    float s12 = d12 / (Nf * Np);
    bool p0 = s01 > THRS, p1 = s02 > THRS, p2 = s12 > THRS;
    bool has = p0 || p1 || p2;

    float m = -3.4e38f;
    if (p0) m = fmaxf(m, s01);
    if (p1) m = fmaxf(m, s02);
    if (p2) m = fmaxf(m, s12);
    if (!has) m = 0.f;
    float e0 = p0 ? expf(s01 - m) : 0.f;
    float e1 = p1 ? expf(s02 - m) : 0.f;
    float e2 = p2 ? expf(s12 - m) : 0.f;
    float inv = 1.f / fmaxf(e0 + e1 + e2, 1e-12f);
    float w0 = e0 * inv, w1 = e1 * inv, w2 = e2 * inv;

    g0 += sbg[0]; g1 += sbg[1]; g2 += sbg[2];
    float gm = fmaxf(g0, fmaxf(g1, g2));
    float x0 = expf(g0 - gm), x1 = expf(g1 - gm), x2 = expf(g2 - gm);
    float xinv = 1.f / (x0 + x1 + x2);
    float fw0 = x0 * xinv, fw1 = x1 * xinv, fw2 = x2 * xinv;

    float rNb = 1.f / Nb, rNf = 1.f / Nf, rNp = 1.f / Np;
    float* Crow = g_C + row * HID;
    float* Zrow = g_Z + row * (2 * HID);
#pragma unroll
    for (int i = 0; i < 2; i++) {
        const float* xb = (const float*)&vb[i];
        const float* xf = (const float*)&vf[i];
        const float* xp = (const float*)&vp[i];
        float4 oc, ow;
        float* poc = (float*)&oc;
        float* pow_ = (float*)&ow;
#pragma unroll
        for (int j = 0; j < 4; j++) {
            float b = xb[j], f = xf[j], p = xp[j];
            float bn = b * rNb, fn = f * rNf, pn = p * rNp;
            float c0 = (bn * fn > THRS) ? 0.5f * (b + f) : 0.f;
            float c1 = (bn * pn > THRS) ? 0.5f * (b + p) : 0.f;
            float c2 = (fn * pn > THRS) ? 0.5f * (f + p) : 0.f;
            float sc = c0 * w0 + c1 * w1 + c2 * w2;
            poc[j]  = tf32r(has ? sc : (b + f + p) * (1.f / 3.f));
            pow_[j] = tf32r(b * fw0 + f * fw1 + p * fw2);
        }
        int c4 = (lane + 32 * i) * 4;
        *(float4*)(Crow + c4) = oc;
        *(float4*)(Zrow + c4) = ow;
    }
}

// ---------------------------------------------------------------------------
// kernel_launch
// ---------------------------------------------------------------------------
extern "C" void kernel_launch(void* const* d_in, const int* in_sizes, int n_in,
                              void* d_out, int out_size)
{
    (void)in_sizes; (void)n_in; (void)out_size;

    const float* X[3]  = {(const float*)d_in[0], (const float*)d_in[1], (const float*)d_in[2]};
    const float* W1[3] = {(const float*)d_in[3], (const float*)d_in[7], (const float*)d_in[11]};
    const float* b1[3] = {(const float*)d_in[4], (const float*)d_in[8], (const float*)d_in[12]};
    const float* W2[3] = {(const float*)d_in[5], (const float*)d_in[9], (const float*)d_in[13]};
    const float* b2[3] = {(const float*)d_in[6], (const float*)d_in[10], (const float*)d_in[14]};
    const float* Wg = (const float*)d_in[15];
    const float* bg = (const float*)d_in[16];
    const float* be = (const float*)d_in[18];
    const float* bf = (const float*)d_in[20];

    void* p;
    float *W1p, *b1p, *W2p, *b2p, *Wep, *Wfp, *Xs, *Hs, *Es, *Cs, *Zs;
    cudaGetSymbolAddress(&p, g_W1p); W1p = (float*)p;
    cudaGetSymbolAddress(&p, g_b1p); b1p = (float*)p;
    cudaGetSymbolAddress(&p, g_W2p); W2p = (float*)p;
    cudaGetSymbolAddress(&p, g_b2p); b2p = (float*)p;
    cudaGetSymbolAddress(&p, g_Wep); Wep = (float*)p;
    cudaGetSymbolAddress(&p, g_Wfp); Wfp = (float*)p;
    cudaGetSymbolAddress(&p, g_X);   Xs  = (float*)p;
    cudaGetSymbolAddress(&p, g_H);   Hs  = (float*)p;
    cudaGetSymbolAddress(&p, g_E);   Es  = (float*)p;
    cudaGetSymbolAddress(&p, g_C);   Cs  = (float*)p;
    cudaGetSymbolAddress(&p, g_Z);   Zs  = (float*)p;

    cudaFuncSetAttribute(mma_gemm<0>, cudaFuncAttributeMaxDynamicSharedMemorySize, SMEM_BYTES);
    cudaFuncSetAttribute(mma_gemm<1>, cudaFuncAttributeMaxDynamicSharedMemorySize, SMEM_BYTES);
    cudaFuncSetAttribute(mma_gemm<2>, cudaFuncAttributeMaxDynamicSharedMemorySize, SMEM_BYTES);

    // 1) pad + round weights; concat b2
    prep_kernel<<<512, 256>>>(W1[0], W1[1], W1[2], b1[0], b1[1], b1[2],
                              W2[0], W2[1], W2[2], b2[0], b2[1], b2[2],
                              (const float*)d_in[17], (const float*)d_in[19]);

    // 2) round inputs into scratch
    {
        dim3 gc(2048, 1, 3);
        conv_kernel<<<gc, 256>>>(X[0], X[1], X[2]);
    }

    const dim3 blk(256);
    // 3) encoders, z-batched over the 3 fingerprints
    {
        dim3 g1(MIDP / 64, BATCH / 256, 3);
        mma_gemm<1><<<g1, blk, SMEM_BYTES>>>(
            Xs, W1p, b1p, Hs, BATCH, MIDP, HID, MIDP, nullptr,
            (size_t)BATCH * HID, (size_t)HID * MIDP, MIDP, (size_t)BATCH * MIDP);
        dim3 g2(HID / 64, BATCH / 256, 3);
        mma_gemm<0><<<g2, blk, SMEM_BYTES>>>(
            Hs, W2p, b2p, Es, BATCH, HID, MIDP, HID, nullptr,
            (size_t)BATCH * MIDP, (size_t)MIDP * HID, HID, (size_t)BATCH * HID);
    }

    // 4) fusion: common -> g_C (tf32), weighted -> g_Z[:,0:256] (tf32)
    fuse_kernel<<<BATCH / 8, 256>>>(Wg, bg);

    // 5) cm = common * sigmoid(common @ We + be) -> g_Z[:,256:512] (tf32)
    dim3 ge(HID / 64, BATCH / 256, 1);
    mma_gemm<2><<<ge, blk, SMEM_BYTES>>>(Cs, Wep, be, Zs + HID,
                                         BATCH, HID, HID, 2 * HID, Cs, 0, 0, 0, 0);

    // 6) fused = Z @ Wf + bf -> d_out (fp32)
    mma_gemm<0><<<ge, blk, SMEM_BYTES>>>(Zs, Wfp, bf, (float*)d_out,
                                         BATCH, HID, 2 * HID, HID, nullptr, 0, 0, 0, 0);
}

// round 12
// speedup vs baseline: 4.1260x; 1.5552x over previous
#include <cuda_runtime.h>
#include <cuda_fp16.h>
#include <math.h>
#include <stdint.h>

// Problem constants
#define BATCH 65536
#define HID   256
#define MID   300
#define MIDP  320
#define THRS  0.6f

// ---------------------------------------------------------------------------
// Scratch (device globals)
// ---------------------------------------------------------------------------
__device__ __half g_W1p[3 * MIDP * HID];              // W1^T [320,256] half x3
__device__ float  g_b1p[3 * MIDP];
__device__ __half g_W2p[3 * HID * MIDP];              // W2^T [256,320] half x3
__device__ float  g_b2p[3 * HID];
__device__ __half g_Wep[HID * HID];                   // We^T [256,256] half
__device__ __half g_Wfp[HID * 2 * HID];               // Wf^T [256,512] half
__device__ __half g_X  [3 * (size_t)BATCH * HID];     // half inputs x3
__device__ __half g_H  [3 * (size_t)BATCH * MIDP];    // hidden x3 (half)
__device__ float  g_E  [3 * (size_t)BATCH * HID];     // encoder outputs (fp32)
__device__ __half g_C  [(size_t)BATCH * HID];         // common (half)
__device__ __half g_Z  [(size_t)BATCH * 2 * HID];     // concat (half)

// ---------------------------------------------------------------------------
// prep: transpose + pad + fp16-round all weights
// ---------------------------------------------------------------------------
__global__ void prep_kernel(const float* __restrict__ W1b, const float* __restrict__ W1f,
                            const float* __restrict__ W1p, const float* __restrict__ b1b,
                            const float* __restrict__ b1f, const float* __restrict__ b1p,
                            const float* __restrict__ W2b, const float* __restrict__ W2f,
                            const float* __restrict__ W2p, const float* __restrict__ b2b,
                            const float* __restrict__ b2f, const float* __restrict__ b2p,
                            const float* __restrict__ We, const float* __restrict__ Wf)
{
    const float* W1s[3] = {W1b, W1f, W1p};
    const float* b1s[3] = {b1b, b1f, b1p};
    const float* W2s[3] = {W2b, W2f, W2p};
    const float* b2s[3] = {b2b, b2f, b2p};
    const int stride = gridDim.x * blockDim.x;
    const int t0 = blockIdx.x * blockDim.x + threadIdx.x;
    for (int e = 0; e < 3; e++) {
        // W1^T [MIDP][HID]: row n, col k
        for (int idx = t0; idx < MIDP * HID; idx += stride) {
            int n = idx / HID, k = idx % HID;
            g_W1p[e * MIDP * HID + idx] =
                (n < MID) ? __float2half_rn(W1s[e][k * MID + n]) : __half(0.f);
        }
        for (int idx = t0; idx < MIDP; idx += stride)
            g_b1p[e * MIDP + idx] = (idx < MID) ? b1s[e][idx] : 0.f;
        // W2^T [HID][MIDP]: row n, col k
        for (int idx = t0; idx < HID * MIDP; idx += stride) {
            int n = idx / MIDP, k = idx % MIDP;
            g_W2p[e * HID * MIDP + idx] =
                (k < MID) ? __float2half_rn(W2s[e][k * HID + n]) : __half(0.f);
        }
        for (int idx = t0; idx < HID; idx += stride)
            g_b2p[e * HID + idx] = b2s[e][idx];
    }
    for (int idx = t0; idx < HID * HID; idx += stride) {
        int n = idx / HID, k = idx % HID;
        g_Wep[idx] = __float2half_rn(We[k * HID + n]);
    }
    for (int idx = t0; idx < HID * 2 * HID; idx += stride) {
        int n = idx / (2 * HID), k = idx % (2 * HID);
        g_Wfp[idx] = __float2half_rn(Wf[k * HID + n]);
    }
}

// ---------------------------------------------------------------------------
// Convert inputs to half scratch
// ---------------------------------------------------------------------------
__global__ void conv_kernel(const float* __restrict__ x0, const float* __restrict__ x1,
                            const float* __restrict__ x2)
{
    const float* xs = (blockIdx.z == 0) ? x0 : (blockIdx.z == 1) ? x1 : x2;
    __half2* dst = (__half2*)(g_X + (size_t)blockIdx.z * BATCH * HID);
    const size_t n4 = (size_t)BATCH * HID / 4;
    const size_t stride = (size_t)gridDim.x * blockDim.x;
    for (size_t i = blockIdx.x * blockDim.x + threadIdx.x; i < n4; i += stride) {
        float4 v = ((const float4*)xs)[i];
        dst[i * 2]     = __floats2half2_rn(v.x, v.y);
        dst[i * 2 + 1] = __floats2half2_rn(v.z, v.w);
    }
}

// ---------------------------------------------------------------------------
// FP16 tensor-core GEMM, cp.async 3-stage pipeline.
// Block 256x64, BK=32 (halves), 8 warps, warp tile 32x64, m16n8k16 mma.sync.
// A [M,K] half row-major; Bw [N,K] half (transposed weights).
// EPI: 0 = fp32 out, 1 = relu -> half out, 2 = mulsrc*sigmoid -> half out.
// z-batched via aZ/bZ/biasZ/cZ element strides.
// ---------------------------------------------------------------------------
#define AP 20                                 // row pitch in uint32 (16 data + 4 pad)
#define STAGE_WORDS (256 * AP + 64 * AP)      // A tile + B tile = 6400 words
#define SMEM_BYTES (3 * STAGE_WORDS * 4)      // 76800

__device__ __forceinline__ void cp16(uint32_t dst, const void* src) {
    asm volatile("cp.async.cg.shared.global [%0], [%1], 16;\n" :: "r"(dst), "l"(src));
}
__device__ __forceinline__ void cp_commit() { asm volatile("cp.async.commit_group;\n"); }
__device__ __forceinline__ void cp_wait1()  { asm volatile("cp.async.wait_group 1;\n"); }

template <int EPI>
__global__ __launch_bounds__(256, 2) void mma_gemm(
    const __half* __restrict__ A, const __half* __restrict__ Bw,
    const float* __restrict__ bias, void* __restrict__ Cout,
    int M, int N, int K, int ldc, const __half* __restrict__ mulsrc,
    size_t aZ, size_t bZ, size_t biasZ, size_t cZ)
{
    extern __shared__ uint32_t smem[];
    const uint32_t smem_b = (uint32_t)__cvta_generic_to_shared(smem);

    A    += (size_t)blockIdx.z * aZ;
    Bw   += (size_t)blockIdx.z * bZ;
    bias += (size_t)blockIdx.z * biasZ;

    const int tid  = threadIdx.x;
    const int lane = tid & 31;
    const int warp = tid >> 5;
    const int g    = lane >> 2;
    const int tq   = lane & 3;
    const int wm0  = warp * 32;
    const int m0   = blockIdx.y * 256;
    const int n0   = blockIdx.x * 64;

    // copy mapping: A rows 0..255, 4 chunks of 16B (8 halves) each
    const int aRow = tid >> 2;            // 0..63 (+64*i)
    const int aChk = (tid & 3) << 3;      // half offset 0,8,16,24
    const int bRow = tid >> 2;            // n row 0..63
    const int bChk = (tid & 3) << 3;

    float acc[2][8][4];
#pragma unroll
    for (int im = 0; im < 2; im++)
#pragma unroll
        for (int in = 0; in < 8; in++)
#pragma unroll
            for (int r = 0; r < 4; r++) acc[im][in][r] = 0.f;

    auto copy_tile = [&](int stage, int k0) {
        uint32_t sb = smem_b + stage * (STAGE_WORDS * 4);
#pragma unroll
        for (int i = 0; i < 4; i++)
            cp16(sb + ((aRow + 64 * i) * AP + (aChk >> 1)) * 4,
                 A + (size_t)(m0 + aRow + 64 * i) * K + k0 + aChk);
        uint32_t bb = sb + 256 * AP * 4;
        cp16(bb + (bRow * AP + (bChk >> 1)) * 4,
             Bw + (size_t)(n0 + bRow) * K + k0 + bChk);
    };

    auto comp = [&](int stage) {
        const uint32_t* As = smem + stage * STAGE_WORDS;
        const uint32_t* Bs = As + 256 * AP;
#pragma unroll
        for (int ks = 0; ks < 2; ks++) {          // 2 x k16
            const int ko = ks * 8;                // uint32 offset within row
            uint32_t af[2][4], bf[8][2];
#pragma unroll
            for (int im = 0; im < 2; im++) {
                int mb = wm0 + im * 16 + g;
                af[im][0] = As[mb * AP + ko + tq];
                af[im][1] = As[(mb + 8) * AP + ko + tq];
                af[im][2] = As[mb * AP + ko + tq + 4];
                af[im][3] = As[(mb + 8) * AP + ko + tq + 4];
            }
#pragma unroll
            for (int in = 0; in < 8; in++) {
                int nn = in * 8 + g;
                bf[in][0] = Bs[nn * AP + ko + tq];
                bf[in][1] = Bs[nn * AP + ko + tq + 4];
            }
#pragma unroll
            for (int im = 0; im < 2; im++)
#pragma unroll
                for (int in = 0; in < 8; in++) {
                    float* c = acc[im][in];
                    asm volatile(
                        "mma.sync.aligned.m16n8k16.row.col.f32.f16.f16.f32 "
                        "{%0,%1,%2,%3}, {%4,%5,%6,%7}, {%8,%9}, {%0,%1,%2,%3};"
                        : "+f"(c[0]), "+f"(c[1]), "+f"(c[2]), "+f"(c[3])
                        : "r"(af[im][0]), "r"(af[im][1]), "r"(af[im][2]), "r"(af[im][3]),
                          "r"(bf[in][0]), "r"(bf[in][1]));
                }
        }
    };

    const int nt = K >> 5;                  // K multiple of 32, nt >= 8
    copy_tile(0, 0);  cp_commit();
    copy_tile(1, 32); cp_commit();

    for (int t = 0; t < nt; t++) {
        cp_wait1();
        __syncthreads();
        if (t + 2 < nt) copy_tile((t + 2) % 3, (t + 2) << 5);
        cp_commit();
        comp(t % 3);
    }

    // epilogue
#pragma unroll
    for (int im = 0; im < 2; im++) {
        int r0 = m0 + wm0 + im * 16 + g;
#pragma unroll
        for (int in = 0; in < 8; in++) {
            int col = n0 + in * 8 + tq * 2;
            float bv0 = bias[col], bv1 = bias[col + 1];
            float v0 = acc[im][in][0] + bv0;
            float v1 = acc[im][in][1] + bv1;
            float v2 = acc[im][in][2] + bv0;
            float v3 = acc[im][in][3] + bv1;
            if (EPI == 0) {
                float* C = (float*)Cout + (size_t)blockIdx.z * cZ;
                *(float2*)(C + (size_t)r0 * ldc + col)       = make_float2(v0, v1);
                *(float2*)(C + (size_t)(r0 + 8) * ldc + col) = make_float2(v2, v3);
            } else {
                if (EPI == 1) {
                    v0 = fmaxf(v0, 0.f); v1 = fmaxf(v1, 0.f);
                    v2 = fmaxf(v2, 0.f); v3 = fmaxf(v3, 0.f);
                } else {
                    __half2 m0h = *(const __half2*)(mulsrc + (size_t)r0 * N + col);
                    __half2 m1h = *(const __half2*)(mulsrc + (size_t)(r0 + 8) * N + col);
                    float2 m0v = __half22float2(m0h);
                    float2 m1v = __half22float2(m1h);
                    v0 = m0v.x / (1.f + expf(-v0));
                    v1 = m0v.y / (1.f + expf(-v1));
                    v2 = m1v.x / (1.f + expf(-v2));
                    v3 = m1v.y / (1.f + expf(-v3));
                }
                __half* C = (__half*)Cout + (size_t)blockIdx.z * cZ;
                *(__half2*)(C + (size_t)r0 * ldc + col)       = __floats2half2_rn(v0, v1);
                *(__half2*)(C + (size_t)(r0 + 8) * ldc + col) = __floats2half2_rn(v2, v3);
            }
        }
    }
}

// ---------------------------------------------------------------------------
// Fusion kernel: one warp per batch row. Reads fp32 E, writes half C and Z.
// ---------------------------------------------------------------------------
__global__ __launch_bounds__(256) void fuse_kernel(const float* __restrict__ Wg,
                                                   const float* __restrict__ bg)
{
    __shared__ float sWg[768 * 3];
    __shared__ float sbg[3];
    const int tid = threadIdx.x;
    for (int i = tid; i < 768 * 3; i += 256) sWg[i] = Wg[i];
    if (tid < 3) sbg[tid] = bg[tid];
    __syncthreads();

    const int warp = tid >> 5;
    const int lane = tid & 31;
    const size_t row = (size_t)blockIdx.x * 8 + warp;

    const float* eb = g_E + row * HID;
    const float* ef = g_E + (size_t)BATCH * HID + row * HID;
    const float* ep = g_E + 2 * (size_t)BATCH * HID + row * HID;

    float4 vb[2], vf[2], vp[2];
#pragma unroll
    for (int i = 0; i < 2; i++) {
        int c4 = (lane + 32 * i) * 4;
        vb[i] = *(const float4*)(eb + c4);
        vf[i] = *(const float4*)(ef + c4);
        vp[i] = *(const float4*)(ep + c4);
    }

    float nb = 0.f, nf = 0.f, npq = 0.f;
    float d01 = 0.f, d02 = 0.f, d12 = 0.f;
    float g0 = 0.f, g1 = 0.f, g2 = 0.f;
#pragma unroll
    for (int i = 0; i < 2; i++) {
        const float* xb = (const float*)&vb[i];
        const float* xf = (const float*)&vf[i];
        const float* xp = (const float*)&vp[i];
#pragma unroll
        for (int j = 0; j < 4; j++) {
            int col = (lane + 32 * i) * 4 + j;
            float b = xb[j], f = xf[j], p = xp[j];
            nb  += b * b;  nf  += f * f;  npq += p * p;
            d01 += b * f;  d02 += b * p;  d12 += f * p;
            const float* wb = sWg + col * 3;
            const float* wf = sWg + (col + 256) * 3;
            const float* wp = sWg + (col + 512) * 3;
            g0 += b * wb[0] + f * wf[0] + p * wp[0];
            g1 += b * wb[1] + f * wf[1] + p * wp[1];
            g2 += b * wb[2] + f * wf[2] + p * wp[2];
        }
    }
#pragma unroll
    for (int o = 16; o > 0; o >>= 1) {
        nb  += __shfl_xor_sync(0xffffffffu, nb,  o);
        nf  += __shfl_xor_sync(0xffffffffu, nf,  o);
        npq += __shfl_xor_sync(0xffffffffu, npq, o);
        d01 += __shfl_xor_sync(0xffffffffu, d01, o);
        d02 += __shfl_xor_sync(0xffffffffu, d02, o);
        d12 += __shfl_xor_sync(0xffffffffu, d12, o);
        g0  += __shfl_xor_sync(0xffffffffu, g0,  o);
        g1  += __shfl_xor_sync(0xffffffffu, g1,  o);
        g2  += __shfl_xor_sync(0xffffffffu, g2,  o);
    }

    float Nb = fmaxf(sqrtf(nb),  1e-12f);
    float Nf = fmaxf(sqrtf(nf),  1e-12f);
    float Np = fmaxf(sqrtf(npq), 1e-12f);
    float s01 = d01 / (Nb * Nf);
    float s02 = d02 / (Nb * Np);
    float s12 = d12 / (Nf * Np);
    bool p0 = s01 > THRS, p1 = s02 > THRS, p2 = s12 > THRS;
    bool has = p0 || p1 || p2;

    float m = -3.4e38f;
    if (p0) m = fmaxf(m, s01);
    if (p1) m = fmaxf(m, s02);
    if (p2) m = fmaxf(m, s12);
    if (!has) m = 0.f;
    float e0 = p0 ? expf(s01 - m) : 0.f;
    float e1 = p1 ? expf(s02 - m) : 0.f;
    float e2 = p2 ? expf(s12 - m) : 0.f;
    float inv = 1.f / fmaxf(e0 + e1 + e2, 1e-12f);
    float w0 = e0 * inv, w1 = e1 * inv, w2 = e2 * inv;

    g0 += sbg[0]; g1 += sbg[1]; g2 += sbg[2];
    float gm = fmaxf(g0, fmaxf(g1, g2));
    float x0 = expf(g0 - gm), x1 = expf(g1 - gm), x2 = expf(g2 - gm);
    float xinv = 1.f / (x0 + x1 + x2);
    float fw0 = x0 * xinv, fw1 = x1 * xinv, fw2 = x2 * xinv;

    float rNb = 1.f / Nb, rNf = 1.f / Nf, rNp = 1.f / Np;
    __half2* Crow = (__half2*)(g_C + row * HID);
    __half2* Zrow = (__half2*)(g_Z + row * (2 * HID));
#pragma unroll
    for (int i = 0; i < 2; i++) {
        const float* xb = (const float*)&vb[i];
        const float* xf = (const float*)&vf[i];
        const float* xp = (const float*)&vp[i];
        float oc[4], ow[4];
#pragma unroll
        for (int j = 0; j < 4; j++) {
            float b = xb[j], f = xf[j], p = xp[j];
            float bn = b * rNb, fn = f * rNf, pn = p * rNp;
            float c0 = (bn * fn > THRS) ? 0.5f * (b + f) : 0.f;
            float c1 = (bn * pn > THRS) ? 0.5f * (b + p) : 0.f;
            float c2 = (fn * pn > THRS) ? 0.5f * (f + p) : 0.f;
            float sc = c0 * w0 + c1 * w1 + c2 * w2;
            oc[j] = has ? sc : (b + f + p) * (1.f / 3.f);
            ow[j] = b * fw0 + f * fw1 + p * fw2;
        }
        int h2 = (lane + 32 * i) * 2;     // half2 index
        Crow[h2]     = __floats2half2_rn(oc[0], oc[1]);
        Crow[h2 + 1] = __floats2half2_rn(oc[2], oc[3]);
        Zrow[h2]     = __floats2half2_rn(ow[0], ow[1]);
        Zrow[h2 + 1] = __floats2half2_rn(ow[2], ow[3]);
    }
}

// ---------------------------------------------------------------------------
// kernel_launch
// ---------------------------------------------------------------------------
extern "C" void kernel_launch(void* const* d_in, const int* in_sizes, int n_in,
                              void* d_out, int out_size)
{
    (void)in_sizes; (void)n_in; (void)out_size;

    const float* X[3]  = {(const float*)d_in[0], (const float*)d_in[1], (const float*)d_in[2]};
    const float* W1[3] = {(const float*)d_in[3], (const float*)d_in[7], (const float*)d_in[11]};
    const float* b1[3] = {(const float*)d_in[4], (const float*)d_in[8], (const float*)d_in[12]};
    const float* W2[3] = {(const float*)d_in[5], (const float*)d_in[9], (const float*)d_in[13]};
    const float* b2[3] = {(const float*)d_in[6], (const float*)d_in[10], (const float*)d_in[14]};
    const float* Wg = (const float*)d_in[15];
    const float* bg = (const float*)d_in[16];
    const float* be = (const float*)d_in[18];
    const float* bf = (const float*)d_in[20];

    void* p;
    __half *W1p, *W2p, *Wep, *Wfp, *Xs, *Hs, *Cs, *Zs;
    float *b1p, *b2p, *Es;
    cudaGetSymbolAddress(&p, g_W1p); W1p = (__half*)p;
    cudaGetSymbolAddress(&p, g_b1p); b1p = (float*)p;
    cudaGetSymbolAddress(&p, g_W2p); W2p = (__half*)p;
    cudaGetSymbolAddress(&p, g_b2p); b2p = (float*)p;
    cudaGetSymbolAddress(&p, g_Wep); Wep = (__half*)p;
    cudaGetSymbolAddress(&p, g_Wfp); Wfp = (__half*)p;
    cudaGetSymbolAddress(&p, g_X);   Xs  = (__half*)p;
    cudaGetSymbolAddress(&p, g_H);   Hs  = (__half*)p;
    cudaGetSymbolAddress(&p, g_E);   Es  = (float*)p;
    cudaGetSymbolAddress(&p, g_C);   Cs  = (__half*)p;
    cudaGetSymbolAddress(&p, g_Z);   Zs  = (__half*)p;

    cudaFuncSetAttribute(mma_gemm<0>, cudaFuncAttributeMaxDynamicSharedMemorySize, SMEM_BYTES);
    cudaFuncSetAttribute(mma_gemm<1>, cudaFuncAttributeMaxDynamicSharedMemorySize, SMEM_BYTES);
    cudaFuncSetAttribute(mma_gemm<2>, cudaFuncAttributeMaxDynamicSharedMemorySize, SMEM_BYTES);

    // 1) weights: transpose + pad + fp16
    prep_kernel<<<512, 256>>>(W1[0], W1[1], W1[2], b1[0], b1[1], b1[2],
                              W2[0], W2[1], W2[2], b2[0], b2[1], b2[2],
                              (const float*)d_in[17], (const float*)d_in[19]);

    // 2) inputs -> half scratch
    {
        dim3 gc(2048, 1, 3);
        conv_kernel<<<gc, 256>>>(X[0], X[1], X[2]);
    }

    const dim3 blk(256);
    // 3) encoders, z-batched: H = relu(X @ W1 + b1) ; E = H @ W2 + b2
    {
        dim3 g1(MIDP / 64, BATCH / 256, 3);
        mma_gemm<1><<<g1, blk, SMEM_BYTES>>>(
            Xs, W1p, b1p, Hs, BATCH, MIDP, HID, MIDP, nullptr,
            (size_t)BATCH * HID, (size_t)MIDP * HID, MIDP, (size_t)BATCH * MIDP);
        dim3 g2(HID / 64, BATCH / 256, 3);
        mma_gemm<0><<<g2, blk, SMEM_BYTES>>>(
            Hs, W2p, b2p, Es, BATCH, HID, MIDP, HID, nullptr,
            (size_t)BATCH * MIDP, (size_t)HID * MIDP, HID, (size_t)BATCH * HID);
    }

    // 4) fusion: common -> g_C (half), weighted -> g_Z[:,0:256] (half)
    fuse_kernel<<<BATCH / 8, 256>>>(Wg, bg);

    // 5) cm = common * sigmoid(common @ We + be) -> g_Z[:,256:512] (half)
    dim3 ge(HID / 64, BATCH / 256, 1);
    mma_gemm<2><<<ge, blk, SMEM_BYTES>>>(Cs, Wep, be, Zs + HID,
                                         BATCH, HID, HID, 2 * HID, Cs, 0, 0, 0, 0);

    // 6) fused = Z @ Wf + bf -> d_out (fp32)
    mma_gemm<0><<<ge, blk, SMEM_BYTES>>>(Zs, Wfp, bf, (float*)d_out,
                                         BATCH, HID, 2 * HID, HID, nullptr, 0, 0, 0, 0);
}

// round 13
// speedup vs baseline: 4.1485x; 1.0054x over previous
#include <cuda_runtime.h>
#include <cuda_fp16.h>
#include <math.h>
#include <stdint.h>

// Problem constants
#define BATCH 65536
#define HID   256
#define MID   300
#define MIDP  320
#define THRS  0.6f

// ---------------------------------------------------------------------------
// Scratch (device globals)
// ---------------------------------------------------------------------------
__device__ __half g_W1p[3 * MIDP * HID];              // W1^T [320,256] half x3
__device__ float  g_b1p[3 * MIDP];
__device__ __half g_W2p[3 * HID * MIDP];              // W2^T [256,320] half x3
__device__ float  g_b2p[3 * HID];
__device__ __half g_Wep[HID * HID];                   // We^T [256,256] half
__device__ __half g_Wfp[HID * 2 * HID];               // Wf^T [256,512] half
__device__ __half g_X  [3 * (size_t)BATCH * HID];     // half inputs x3
__device__ __half g_H  [3 * (size_t)BATCH * MIDP];    // hidden x3 (half)
__device__ float  g_E  [3 * (size_t)BATCH * HID];     // encoder outputs (fp32)
__device__ __half g_C  [(size_t)BATCH * HID];         // common (half)
__device__ __half g_Z  [(size_t)BATCH * 2 * HID];     // concat (half)

// ---------------------------------------------------------------------------
// prep: transpose + pad + fp16-round all weights
// ---------------------------------------------------------------------------
__global__ void prep_kernel(const float* __restrict__ W1b, const float* __restrict__ W1f,
                            const float* __restrict__ W1p, const float* __restrict__ b1b,
                            const float* __restrict__ b1f, const float* __restrict__ b1p,
                            const float* __restrict__ W2b, const float* __restrict__ W2f,
                            const float* __restrict__ W2p, const float* __restrict__ b2b,
                            const float* __restrict__ b2f, const float* __restrict__ b2p,
                            const float* __restrict__ We, const float* __restrict__ Wf)
{
    const float* W1s[3] = {W1b, W1f, W1p};
    const float* b1s[3] = {b1b, b1f, b1p};
    const float* W2s[3] = {W2b, W2f, W2p};
    const float* b2s[3] = {b2b, b2f, b2p};
    const int stride = gridDim.x * blockDim.x;
    const int t0 = blockIdx.x * blockDim.x + threadIdx.x;
    for (int e = 0; e < 3; e++) {
        // W1^T [MIDP][HID]: row n, col k
        for (int idx = t0; idx < MIDP * HID; idx += stride) {
            int n = idx / HID, k = idx % HID;
            g_W1p[e * MIDP * HID + idx] =
                (n < MID) ? __float2half_rn(W1s[e][k * MID + n]) : __half(0.f);
        }
        for (int idx = t0; idx < MIDP; idx += stride)
            g_b1p[e * MIDP + idx] = (idx < MID) ? b1s[e][idx] : 0.f;
        // W2^T [HID][MIDP]: row n, col k
        for (int idx = t0; idx < HID * MIDP; idx += stride) {
            int n = idx / MIDP, k = idx % MIDP;
            g_W2p[e * HID * MIDP + idx] =
                (k < MID) ? __float2half_rn(W2s[e][k * HID + n]) : __half(0.f);
        }
        for (int idx = t0; idx < HID; idx += stride)
            g_b2p[e * HID + idx] = b2s[e][idx];
    }
    for (int idx = t0; idx < HID * HID; idx += stride) {
        int n = idx / HID, k = idx % HID;
        g_Wep[idx] = __float2half_rn(We[k * HID + n]);
    }
    for (int idx = t0; idx < HID * 2 * HID; idx += stride) {
        int n = idx / (2 * HID), k = idx % (2 * HID);
        g_Wfp[idx] = __float2half_rn(Wf[k * HID + n]);
    }
}

// ---------------------------------------------------------------------------
// Convert inputs to half scratch
// ---------------------------------------------------------------------------
__global__ void conv_kernel(const float* __restrict__ x0, const float* __restrict__ x1,
                            const float* __restrict__ x2)
{
    const float* xs = (blockIdx.z == 0) ? x0 : (blockIdx.z == 1) ? x1 : x2;
    __half2* dst = (__half2*)(g_X + (size_t)blockIdx.z * BATCH * HID);
    const size_t n4 = (size_t)BATCH * HID / 4;
    const size_t stride = (size_t)gridDim.x * blockDim.x;
    for (size_t i = blockIdx.x * blockDim.x + threadIdx.x; i < n4; i += stride) {
        float4 v = ((const float4*)xs)[i];
        dst[i * 2]     = __floats2half2_rn(v.x, v.y);
        dst[i * 2 + 1] = __floats2half2_rn(v.z, v.w);
    }
}

// ---------------------------------------------------------------------------
// FP16 tensor-core GEMM, cp.async 3-stage pipeline + ldmatrix fragment loads.
// Block 256x64, BK=32 (halves), 8 warps, warp tile 32x64, m16n8k16 mma.sync.
// A [M,K] half row-major; Bw [N,K] half (transposed weights).
// EPI: 0 = fp32 out, 1 = relu -> half out, 2 = mulsrc*sigmoid -> half out.
// ---------------------------------------------------------------------------
#define AP 20                                 // row pitch in uint32 (16 data + 4 pad)
#define STAGE_WORDS (256 * AP + 64 * AP)      // A tile + B tile = 6400 words
#define SMEM_BYTES (3 * STAGE_WORDS * 4)      // 76800

__device__ __forceinline__ void cp16(uint32_t dst, const void* src) {
    asm volatile("cp.async.cg.shared.global [%0], [%1], 16;\n" :: "r"(dst), "l"(src));
}
__device__ __forceinline__ void cp_commit() { asm volatile("cp.async.commit_group;\n"); }
__device__ __forceinline__ void cp_wait1()  { asm volatile("cp.async.wait_group 1;\n"); }

__device__ __forceinline__ void ldsm4(uint32_t& r0, uint32_t& r1, uint32_t& r2,
                                      uint32_t& r3, uint32_t addr) {
    asm volatile("ldmatrix.sync.aligned.m8n8.x4.shared.b16 {%0,%1,%2,%3}, [%4];"
                 : "=r"(r0), "=r"(r1), "=r"(r2), "=r"(r3) : "r"(addr));
}

template <int EPI>
__global__ __launch_bounds__(256, 2) void mma_gemm(
    const __half* __restrict__ A, const __half* __restrict__ Bw,
    const float* __restrict__ bias, void* __restrict__ Cout,
    int M, int N, int K, int ldc, const __half* __restrict__ mulsrc,
    size_t aZ, size_t bZ, size_t biasZ, size_t cZ)
{
    extern __shared__ uint32_t smem[];
    const uint32_t smem_b = (uint32_t)__cvta_generic_to_shared(smem);

    A    += (size_t)blockIdx.z * aZ;
    Bw   += (size_t)blockIdx.z * bZ;
    bias += (size_t)blockIdx.z * biasZ;

    const int tid  = threadIdx.x;
    const int lane = tid & 31;
    const int warp = tid >> 5;
    const int g    = lane >> 2;
    const int tq   = lane & 3;
    const int wm0  = warp * 32;
    const int m0   = blockIdx.y * 256;
    const int n0   = blockIdx.x * 64;

    // copy mapping
    const int aRow = tid >> 2;            // 0..63 (+64*i)
    const int aChk = (tid & 3) << 3;      // half offset 0,8,16,24
    const int bRow = tid >> 2;
    const int bChk = (tid & 3) << 3;

    // ldmatrix per-lane addressing
    const int lr = lane & 15;             // row within 16-row group
    const int lh = (lane >> 4) << 2;      // 0 or 4 words (k half select)

    float acc[2][8][4];
#pragma unroll
    for (int im = 0; im < 2; im++)
#pragma unroll
        for (int in = 0; in < 8; in++)
#pragma unroll
            for (int r = 0; r < 4; r++) acc[im][in][r] = 0.f;

    auto copy_tile = [&](int stage, int k0) {
        uint32_t sb = smem_b + stage * (STAGE_WORDS * 4);
#pragma unroll
        for (int i = 0; i < 4; i++)
            cp16(sb + ((aRow + 64 * i) * AP + (aChk >> 1)) * 4,
                 A + (size_t)(m0 + aRow + 64 * i) * K + k0 + aChk);
        uint32_t bb = sb + 256 * AP * 4;
        cp16(bb + (bRow * AP + (bChk >> 1)) * 4,
             Bw + (size_t)(n0 + bRow) * K + k0 + bChk);
    };

    auto comp = [&](int stage) {
        const uint32_t As_b = smem_b + stage * (STAGE_WORDS * 4);
        const uint32_t Bs_b = As_b + 256 * AP * 4;
#pragma unroll
        for (int ks = 0; ks < 2; ks++) {          // 2 x k16
            const int ko = ks * 8;                // uint32 offset within row
            uint32_t af[2][4], bf[8][2];
#pragma unroll
            for (int im = 0; im < 2; im++) {
                uint32_t addr = As_b + (((wm0 + im * 16 + lr) * AP) + ko + lh) * 4;
                ldsm4(af[im][0], af[im][1], af[im][2], af[im][3], addr);
            }
#pragma unroll
            for (int q = 0; q < 4; q++) {
                uint32_t addr = Bs_b + (((q * 16 + lr) * AP) + ko + lh) * 4;
                ldsm4(bf[2 * q][0], bf[2 * q + 1][0],
                      bf[2 * q][1], bf[2 * q + 1][1], addr);
            }
#pragma unroll
            for (int im = 0; im < 2; im++)
#pragma unroll
                for (int in = 0; in < 8; in++) {
                    float* c = acc[im][in];
                    asm volatile(
                        "mma.sync.aligned.m16n8k16.row.col.f32.f16.f16.f32 "
                        "{%0,%1,%2,%3}, {%4,%5,%6,%7}, {%8,%9}, {%0,%1,%2,%3};"
                        : "+f"(c[0]), "+f"(c[1]), "+f"(c[2]), "+f"(c[3])
                        : "r"(af[im][0]), "r"(af[im][1]), "r"(af[im][2]), "r"(af[im][3]),
                          "r"(bf[in][0]), "r"(bf[in][1]));
                }
        }
    };

    const int nt = K >> 5;                  // K multiple of 32, nt >= 8
    copy_tile(0, 0);  cp_commit();
    copy_tile(1, 32); cp_commit();

    for (int t = 0; t < nt; t++) {
        cp_wait1();
        __syncthreads();
        if (t + 2 < nt) copy_tile((t + 2) % 3, (t + 2) << 5);
        cp_commit();
        comp(t % 3);
    }

    // epilogue
#pragma unroll
    for (int im = 0; im < 2; im++) {
        int r0 = m0 + wm0 + im * 16 + g;
#pragma unroll
        for (int in = 0; in < 8; in++) {
            int col = n0 + in * 8 + tq * 2;
            float bv0 = bias[col], bv1 = bias[col + 1];
            float v0 = acc[im][in][0] + bv0;
            float v1 = acc[im][in][1] + bv1;
            float v2 = acc[im][in][2] + bv0;
            float v3 = acc[im][in][3] + bv1;
            if (EPI == 0) {
                float* C = (float*)Cout + (size_t)blockIdx.z * cZ;
                *(float2*)(C + (size_t)r0 * ldc + col)       = make_float2(v0, v1);
                *(float2*)(C + (size_t)(r0 + 8) * ldc + col) = make_float2(v2, v3);
            } else {
                if (EPI == 1) {
                    v0 = fmaxf(v0, 0.f); v1 = fmaxf(v1, 0.f);
                    v2 = fmaxf(v2, 0.f); v3 = fmaxf(v3, 0.f);
                } else {
                    __half2 m0h = *(const __half2*)(mulsrc + (size_t)r0 * N + col);
                    __half2 m1h = *(const __half2*)(mulsrc + (size_t)(r0 + 8) * N + col);
                    float2 m0v = __half22float2(m0h);
                    float2 m1v = __half22float2(m1h);
                    v0 = m0v.x / (1.f + expf(-v0));
                    v1 = m0v.y / (1.f + expf(-v1));
                    v2 = m1v.x / (1.f + expf(-v2));
                    v3 = m1v.y / (1.f + expf(-v3));
                }
                __half* C = (__half*)Cout + (size_t)blockIdx.z * cZ;
                *(__half2*)(C + (size_t)r0 * ldc + col)       = __floats2half2_rn(v0, v1);
                *(__half2*)(C + (size_t)(r0 + 8) * ldc + col) = __floats2half2_rn(v2, v3);
            }
        }
    }
}

// ---------------------------------------------------------------------------
// Fusion kernel: one warp per batch row. Reads fp32 E, writes half C and Z.
// ---------------------------------------------------------------------------
__global__ __launch_bounds__(256) void fuse_kernel(const float* __restrict__ Wg,
                                                   const float* __restrict__ bg)
{
    __shared__ float sWg[768 * 3];
    __shared__ float sbg[3];
    const int tid = threadIdx.x;
    for (int i = tid; i < 768 * 3; i += 256) sWg[i] = Wg[i];
    if (tid < 3) sbg[tid] = bg[tid];
    __syncthreads();

    const int warp = tid >> 5;
    const int lane = tid & 31;
    const size_t row = (size_t)blockIdx.x * 8 + warp;

    const float* eb = g_E + row * HID;
    const float* ef = g_E + (size_t)BATCH * HID + row * HID;
    const float* ep = g_E + 2 * (size_t)BATCH * HID + row * HID;

    float4 vb[2], vf[2], vp[2];
#pragma unroll
    for (int i = 0; i < 2; i++) {
        int c4 = (lane + 32 * i) * 4;
        vb[i] = *(const float4*)(eb + c4);
        vf[i] = *(const float4*)(ef + c4);
        vp[i] = *(const float4*)(ep + c4);
    }

    float nb = 0.f, nf = 0.f, npq = 0.f;
    float d01 = 0.f, d02 = 0.f, d12 = 0.f;
    float g0 = 0.f, g1 = 0.f, g2 = 0.f;
#pragma unroll
    for (int i = 0; i < 2; i++) {
        const float* xb = (const float*)&vb[i];
        const float* xf = (const float*)&vf[i];
        const float* xp = (const float*)&vp[i];
#pragma unroll
        for (int j = 0; j < 4; j++) {
            int col = (lane + 32 * i) * 4 + j;
            float b = xb[j], f = xf[j], p = xp[j];
            nb  += b * b;  nf  += f * f;  npq += p * p;
            d01 += b * f;  d02 += b * p;  d12 += f * p;
            const float* wb = sWg + col * 3;
            const float* wf = sWg + (col + 256) * 3;
            const float* wp = sWg + (col + 512) * 3;
            g0 += b * wb[0] + f * wf[0] + p * wp[0];
            g1 += b * wb[1] + f * wf[1] + p * wp[1];
            g2 += b * wb[2] + f * wf[2] + p * wp[2];
        }
    }
#pragma unroll
    for (int o = 16; o > 0; o >>= 1) {
        nb  += __shfl_xor_sync(0xffffffffu, nb,  o);
        nf  += __shfl_xor_sync(0xffffffffu, nf,  o);
        npq += __shfl_xor_sync(0xffffffffu, npq, o);
        d01 += __shfl_xor_sync(0xffffffffu, d01, o);
        d02 += __shfl_xor_sync(0xffffffffu, d02, o);
        d12 += __shfl_xor_sync(0xffffffffu, d12, o);
        g0  += __shfl_xor_sync(0xffffffffu, g0,  o);
        g1  += __shfl_xor_sync(0xffffffffu, g1,  o);
        g2  += __shfl_xor_sync(0xffffffffu, g2,  o);
    }

    float Nb = fmaxf(sqrtf(nb),  1e-12f);
    float Nf = fmaxf(sqrtf(nf),  1e-12f);
    float Np = fmaxf(sqrtf(npq), 1e-12f);
    float s01 = d01 / (Nb * Nf);
    float s02 = d02 / (Nb * Np);
    float s12 = d12 / (Nf * Np);
    bool p0 = s01 > THRS, p1 = s02 > THRS, p2 = s12 > THRS;
    bool has = p0 || p1 || p2;

    float m = -3.4e38f;
    if (p0) m = fmaxf(m, s01);
    if (p1) m = fmaxf(m, s02);
    if (p2) m = fmaxf(m, s12);
    if (!has) m = 0.f;
    float e0 = p0 ? expf(s01 - m) : 0.f;
    float e1 = p1 ? expf(s02 - m) : 0.f;
    float e2 = p2 ? expf(s12 - m) : 0.f;
    float inv = 1.f / fmaxf(e0 + e1 + e2, 1e-12f);
    float w0 = e0 * inv, w1 = e1 * inv, w2 = e2 * inv;

    g0 += sbg[0]; g1 += sbg[1]; g2 += sbg[2];
    float gm = fmaxf(g0, fmaxf(g1, g2));
    float x0 = expf(g0 - gm), x1 = expf(g1 - gm), x2 = expf(g2 - gm);
    float xinv = 1.f / (x0 + x1 + x2);
    float fw0 = x0 * xinv, fw1 = x1 * xinv, fw2 = x2 * xinv;

    float rNb = 1.f / Nb, rNf = 1.f / Nf, rNp = 1.f / Np;
    __half2* Crow = (__half2*)(g_C + row * HID);
    __half2* Zrow = (__half2*)(g_Z + row * (2 * HID));
#pragma unroll
    for (int i = 0; i < 2; i++) {
        const float* xb = (const float*)&vb[i];
        const float* xf = (const float*)&vf[i];
        const float* xp = (const float*)&vp[i];
        float oc[4], ow[4];
#pragma unroll
        for (int j = 0; j < 4; j++) {
            float b = xb[j], f = xf[j], p = xp[j];
            float bn = b * rNb, fn = f * rNf, pn = p * rNp;
            float c0 = (bn * fn > THRS) ? 0.5f * (b + f) : 0.f;
            float c1 = (bn * pn > THRS) ? 0.5f * (b + p) : 0.f;
            float c2 = (fn * pn > THRS) ? 0.5f * (f + p) : 0.f;
            float sc = c0 * w0 + c1 * w1 + c2 * w2;
            oc[j] = has ? sc : (b + f + p) * (1.f / 3.f);
            ow[j] = b * fw0 + f * fw1 + p * fw2;
        }
        int h2 = (lane + 32 * i) * 2;     // half2 index
        Crow[h2]     = __floats2half2_rn(oc[0], oc[1]);
        Crow[h2 + 1] = __floats2half2_rn(oc[2], oc[3]);
        Zrow[h2]     = __floats2half2_rn(ow[0], ow[1]);
        Zrow[h2 + 1] = __floats2half2_rn(ow[2], ow[3]);
    }
}

// ---------------------------------------------------------------------------
// kernel_launch
// ---------------------------------------------------------------------------
extern "C" void kernel_launch(void* const* d_in, const int* in_sizes, int n_in,
                              void* d_out, int out_size)
{
    (void)in_sizes; (void)n_in; (void)out_size;

    const float* X[3]  = {(const float*)d_in[0], (const float*)d_in[1], (const float*)d_in[2]};
    const float* W1[3] = {(const float*)d_in[3], (const float*)d_in[7], (const float*)d_in[11]};
    const float* b1[3] = {(const float*)d_in[4], (const float*)d_in[8], (const float*)d_in[12]};
    const float* W2[3] = {(const float*)d_in[5], (const float*)d_in[9], (const float*)d_in[13]};
    const float* b2[3] = {(const float*)d_in[6], (const float*)d_in[10], (const float*)d_in[14]};
    const float* Wg = (const float*)d_in[15];
    const float* bg = (const float*)d_in[16];
    const float* be = (const float*)d_in[18];
    const float* bf = (const float*)d_in[20];

    void* p;
    __half *W1p, *W2p, *Wep, *Wfp, *Xs, *Hs, *Cs, *Zs;
    float *b1p, *b2p, *Es;
    cudaGetSymbolAddress(&p, g_W1p); W1p = (__half*)p;
    cudaGetSymbolAddress(&p, g_b1p); b1p = (float*)p;
    cudaGetSymbolAddress(&p, g_W2p); W2p = (__half*)p;
    cudaGetSymbolAddress(&p, g_b2p); b2p = (float*)p;
    cudaGetSymbolAddress(&p, g_Wep); Wep = (__half*)p;
    cudaGetSymbolAddress(&p, g_Wfp); Wfp = (__half*)p;
    cudaGetSymbolAddress(&p, g_X);   Xs  = (__half*)p;
    cudaGetSymbolAddress(&p, g_H);   Hs  = (__half*)p;
    cudaGetSymbolAddress(&p, g_E);   Es  = (float*)p;
    cudaGetSymbolAddress(&p, g_C);   Cs  = (__half*)p;
    cudaGetSymbolAddress(&p, g_Z);   Zs  = (__half*)p;

    cudaFuncSetAttribute(mma_gemm<0>, cudaFuncAttributeMaxDynamicSharedMemorySize, SMEM_BYTES);
    cudaFuncSetAttribute(mma_gemm<1>, cudaFuncAttributeMaxDynamicSharedMemorySize, SMEM_BYTES);
    cudaFuncSetAttribute(mma_gemm<2>, cudaFuncAttributeMaxDynamicSharedMemorySize, SMEM_BYTES);

    // 1) weights: transpose + pad + fp16
    prep_kernel<<<512, 256>>>(W1[0], W1[1], W1[2], b1[0], b1[1], b1[2],
                              W2[0], W2[1], W2[2], b2[0], b2[1], b2[2],
                              (const float*)d_in[17], (const float*)d_in[19]);

    // 2) inputs -> half scratch
    {
        dim3 gc(2048, 1, 3);
        conv_kernel<<<gc, 256>>>(X[0], X[1], X[2]);
    }

    const dim3 blk(256);
    // 3) encoders, z-batched: H = relu(X @ W1 + b1) ; E = H @ W2 + b2
    {
        dim3 g1(MIDP / 64, BATCH / 256, 3);
        mma_gemm<1><<<g1, blk, SMEM_BYTES>>>(
            Xs, W1p, b1p, Hs, BATCH, MIDP, HID, MIDP, nullptr,
            (size_t)BATCH * HID, (size_t)MIDP * HID, MIDP, (size_t)BATCH * MIDP);
        dim3 g2(HID / 64, BATCH / 256, 3);
        mma_gemm<0><<<g2, blk, SMEM_BYTES>>>(
            Hs, W2p, b2p, Es, BATCH, HID, MIDP, HID, nullptr,
            (size_t)BATCH * MIDP, (size_t)HID * MIDP, HID, (size_t)BATCH * HID);
    }

    // 4) fusion: common -> g_C (half), weighted -> g_Z[:,0:256] (half)
    fuse_kernel<<<BATCH / 8, 256>>>(Wg, bg);

    // 5) cm = common * sigmoid(common @ We + be) -> g_Z[:,256:512] (half)
    dim3 ge(HID / 64, BATCH / 256, 1);
    mma_gemm<2><<<ge, blk, SMEM_BYTES>>>(Cs, Wep, be, Zs + HID,
                                         BATCH, HID, HID, 2 * HID, Cs, 0, 0, 0, 0);

    // 6) fused = Z @ Wf + bf -> d_out (fp32)
    mma_gemm<0><<<ge, blk, SMEM_BYTES>>>(Zs, Wfp, bf, (float*)d_out,
                                         BATCH, HID, 2 * HID, HID, nullptr, 0, 0, 0, 0);
}